// round 1
// baseline (speedup 1.0000x reference)
#include <cuda_runtime.h>
#include <math.h>

#define B_  8
#define C_  512
#define T_  1024
#define E_  1024
#define H_  8
#define HD_ 64
#define QK_ 512
#define EV_ 128

// scale = log(1024)/log(512)/sqrt(64) = (10/9)/8
#define SCALE_ 0.13888888888888889f

// ---------------- scratch (device globals; no runtime allocation) ------------
static __device__ float g_uv[(size_t)B_ * 2 * E_ * T_];   // [b, o(0..2047), t] ; u = o<1024, v = o>=1024
static __device__ float g_zq[(size_t)B_ * QK_ * T_];      // [b, o, t]
static __device__ float g_zk[(size_t)B_ * QK_ * T_];      // [b, o, t]
static __device__ float g_att[(size_t)B_ * H_ * T_ * EV_];// [b, h, t, e']
static __device__ float g_y[(size_t)B_ * C_ * T_];        // [b, c, t]

// ---------------- SGEMM tiling ----------------
#define BM 128
#define BN 128
#define BKd 16
#define SPAD 132   // BM + 4 padding to dodge smem bank conflicts

// =============================================================================
// GEMM1: uv[b,o,t] = silu( W_in[o,c] @ x[b,c,t] + b_in[o] )   M=2048 K=512 N=1024
// =============================================================================
__global__ __launch_bounds__(256) void gemm_uv_kernel(
    const float* __restrict__ W, const float* __restrict__ x,
    const float* __restrict__ bias)
{
    __shared__ __align__(16) float As[BKd * SPAD];
    __shared__ __align__(16) float Bs[BKd * SPAD];
    const int b   = blockIdx.z;
    const int m0  = blockIdx.y * BM;
    const int n0  = blockIdx.x * BN;
    const int tid = threadIdx.x;
    const int tm0 = (tid >> 4) << 3;
    const int tn0 = (tid & 15) << 3;
    const float* xb = x + (size_t)b * C_ * T_;

    float acc[8][8];
#pragma unroll
    for (int i = 0; i < 8; i++)
#pragma unroll
        for (int j = 0; j < 8; j++) acc[i][j] = 0.f;

    for (int k0 = 0; k0 < C_; k0 += BKd) {
#pragma unroll
        for (int p = 0; p < 2; p++) {
            int idx = tid + 256 * p;
            int row = idx >> 2;
            int kq  = (idx & 3) << 2;
            float4 a4 = *(const float4*)(W + (size_t)(m0 + row) * C_ + k0 + kq);
            As[(kq + 0) * SPAD + row] = a4.x;
            As[(kq + 1) * SPAD + row] = a4.y;
            As[(kq + 2) * SPAD + row] = a4.z;
            As[(kq + 3) * SPAD + row] = a4.w;
        }
#pragma unroll
        for (int p = 0; p < 2; p++) {
            int idx = tid + 256 * p;
            int kk  = idx >> 5;
            int nq  = (idx & 31) << 2;
            *(float4*)(Bs + kk * SPAD + nq) =
                *(const float4*)(xb + (size_t)(k0 + kk) * T_ + n0 + nq);
        }
        __syncthreads();
#pragma unroll
        for (int k = 0; k < BKd; k++) {
            float4 a0 = *(const float4*)(As + k * SPAD + tm0);
            float4 a1 = *(const float4*)(As + k * SPAD + tm0 + 4);
            float4 b0 = *(const float4*)(Bs + k * SPAD + tn0);
            float4 b1 = *(const float4*)(Bs + k * SPAD + tn0 + 4);
            float av[8] = {a0.x, a0.y, a0.z, a0.w, a1.x, a1.y, a1.z, a1.w};
            float bv[8] = {b0.x, b0.y, b0.z, b0.w, b1.x, b1.y, b1.z, b1.w};
#pragma unroll
            for (int i = 0; i < 8; i++)
#pragma unroll
                for (int j = 0; j < 8; j++) acc[i][j] += av[i] * bv[j];
        }
        __syncthreads();
    }

    float* outp = g_uv + (size_t)b * 2 * E_ * T_;
#pragma unroll
    for (int i = 0; i < 8; i++) {
        int m = m0 + tm0 + i;
        float bi = bias[m];
        float v[8];
#pragma unroll
        for (int j = 0; j < 8; j++) {
            float t = acc[i][j] + bi;
            v[j] = t / (1.f + __expf(-t));   // silu
        }
        float4 w0 = {v[0], v[1], v[2], v[3]};
        float4 w1 = {v[4], v[5], v[6], v[7]};
        *(float4*)(outp + (size_t)m * T_ + n0 + tn0)     = w0;
        *(float4*)(outp + (size_t)m * T_ + n0 + tn0 + 4) = w1;
    }
}

// =============================================================================
// GEMM2: z = W_attn @ x + b_attn ; q = z*w_q+b_q ; k = z*w_k+b_k   M=512 K=512
// =============================================================================
__global__ __launch_bounds__(256) void gemm_qk_kernel(
    const float* __restrict__ W, const float* __restrict__ x,
    const float* __restrict__ bias,
    const float* __restrict__ wq, const float* __restrict__ bq,
    const float* __restrict__ wk, const float* __restrict__ bk)
{
    __shared__ __align__(16) float As[BKd * SPAD];
    __shared__ __align__(16) float Bs[BKd * SPAD];
    const int b   = blockIdx.z;
    const int m0  = blockIdx.y * BM;
    const int n0  = blockIdx.x * BN;
    const int tid = threadIdx.x;
    const int tm0 = (tid >> 4) << 3;
    const int tn0 = (tid & 15) << 3;
    const float* xb = x + (size_t)b * C_ * T_;

    float acc[8][8];
#pragma unroll
    for (int i = 0; i < 8; i++)
#pragma unroll
        for (int j = 0; j < 8; j++) acc[i][j] = 0.f;

    for (int k0 = 0; k0 < C_; k0 += BKd) {
#pragma unroll
        for (int p = 0; p < 2; p++) {
            int idx = tid + 256 * p;
            int row = idx >> 2;
            int kq  = (idx & 3) << 2;
            float4 a4 = *(const float4*)(W + (size_t)(m0 + row) * C_ + k0 + kq);
            As[(kq + 0) * SPAD + row] = a4.x;
            As[(kq + 1) * SPAD + row] = a4.y;
            As[(kq + 2) * SPAD + row] = a4.z;
            As[(kq + 3) * SPAD + row] = a4.w;
        }
#pragma unroll
        for (int p = 0; p < 2; p++) {
            int idx = tid + 256 * p;
            int kk  = idx >> 5;
            int nq  = (idx & 31) << 2;
            *(float4*)(Bs + kk * SPAD + nq) =
                *(const float4*)(xb + (size_t)(k0 + kk) * T_ + n0 + nq);
        }
        __syncthreads();
#pragma unroll
        for (int k = 0; k < BKd; k++) {
            float4 a0 = *(const float4*)(As + k * SPAD + tm0);
            float4 a1 = *(const float4*)(As + k * SPAD + tm0 + 4);
            float4 b0 = *(const float4*)(Bs + k * SPAD + tn0);
            float4 b1 = *(const float4*)(Bs + k * SPAD + tn0 + 4);
            float av[8] = {a0.x, a0.y, a0.z, a0.w, a1.x, a1.y, a1.z, a1.w};
            float bv[8] = {b0.x, b0.y, b0.z, b0.w, b1.x, b1.y, b1.z, b1.w};
#pragma unroll
            for (int i = 0; i < 8; i++)
#pragma unroll
                for (int j = 0; j < 8; j++) acc[i][j] += av[i] * bv[j];
        }
        __syncthreads();
    }

    float* qp = g_zq + (size_t)b * QK_ * T_;
    float* kp = g_zk + (size_t)b * QK_ * T_;
#pragma unroll
    for (int i = 0; i < 8; i++) {
        int m = m0 + tm0 + i;
        float bi = bias[m];
        float wqm = wq[m], bqm = bq[m], wkm = wk[m], bkm = bk[m];
        float qv[8], kv[8];
#pragma unroll
        for (int j = 0; j < 8; j++) {
            float z = acc[i][j] + bi;
            qv[j] = z * wqm + bqm;
            kv[j] = z * wkm + bkm;
        }
        float4 q0 = {qv[0], qv[1], qv[2], qv[3]};
        float4 q1 = {qv[4], qv[5], qv[6], qv[7]};
        float4 k0v = {kv[0], kv[1], kv[2], kv[3]};
        float4 k1v = {kv[4], kv[5], kv[6], kv[7]};
        *(float4*)(qp + (size_t)m * T_ + n0 + tn0)     = q0;
        *(float4*)(qp + (size_t)m * T_ + n0 + tn0 + 4) = q1;
        *(float4*)(kp + (size_t)m * T_ + n0 + tn0)     = k0v;
        *(float4*)(kp + (size_t)m * T_ + n0 + tn0 + 4) = k1v;
    }
}

// =============================================================================
// Flash attention (fp32, online softmax). BQ=64 rows per block, BK=64 k-tiles.
// q,k stored as [b, h*64+d, t]; v stored in g_uv at channel 1024 + h*128 + e.
// Writes o in [b, h, t, e'] layout (coalesced).
// =============================================================================
#define ATTN_SMEM_FLOATS (4160 + 4160 + 8192 + 4160 + 192)
#define ATTN_SMEM_BYTES  (ATTN_SMEM_FLOATS * 4)

__global__ __launch_bounds__(256) void attn_kernel()
{
    extern __shared__ __align__(16) float sm[];
    float* qs   = sm;            // [64][65]
    float* ks   = sm + 4160;     // [64][65]
    float* vs   = sm + 8320;     // [64][128]
    float* ps   = sm + 16512;    // [64][65]
    float* mrow = sm + 20672;    // [64]
    float* lrow = sm + 20736;    // [64]
    float* arow = sm + 20800;    // [64]

    const int b  = blockIdx.z;
    const int h  = blockIdx.y;
    const int qt = blockIdx.x;
    const int tid = threadIdx.x;

    const float* qbase = g_zq + (size_t)(b * QK_ + h * HD_) * T_;
    const float* kbase = g_zk + (size_t)(b * QK_ + h * HD_) * T_;
    const float* vbase = g_uv + (size_t)(b * 2 * E_ + E_ + h * EV_) * T_;

    // load q tile: [64 d][64 t] from global, store transposed qs[t_local][d]
#pragma unroll
    for (int p = 0; p < 4; p++) {
        int idx = tid + 256 * p;
        int d  = idx >> 4;
        int tq = (idx & 15) << 2;
        float4 q4 = *(const float4*)(qbase + (size_t)d * T_ + qt * 64 + tq);
        qs[(tq + 0) * 65 + d] = q4.x;
        qs[(tq + 1) * 65 + d] = q4.y;
        qs[(tq + 2) * 65 + d] = q4.z;
        qs[(tq + 3) * 65 + d] = q4.w;
    }
    if (tid < 64) { mrow[tid] = -1e30f; lrow[tid] = 0.f; }

    float acc[4][8];
#pragma unroll
    for (int i = 0; i < 4; i++)
#pragma unroll
        for (int j = 0; j < 8; j++) acc[i][j] = 0.f;

    const int r0 = (tid >> 4) << 2;   // 4 q-rows per thread group
    const int c0 = (tid & 15) << 2;   // 4 score cols (score phase)
    const int e0 = (tid & 15) << 3;   // 8 v cols (PV phase)
    __syncthreads();

    for (int kt = 0; kt < 16; kt++) {
        const int kt0 = kt * 64;
        // load k tile transposed -> ks[t_local][d]
#pragma unroll
        for (int p = 0; p < 4; p++) {
            int idx = tid + 256 * p;
            int d  = idx >> 4;
            int tq = (idx & 15) << 2;
            float4 k4 = *(const float4*)(kbase + (size_t)d * T_ + kt0 + tq);
            ks[(tq + 0) * 65 + d] = k4.x;
            ks[(tq + 1) * 65 + d] = k4.y;
            ks[(tq + 2) * 65 + d] = k4.z;
            ks[(tq + 3) * 65 + d] = k4.w;
        }
        // load v tile transposed -> vs[t_local][e]
#pragma unroll
        for (int p = 0; p < 8; p++) {
            int idx = tid + 256 * p;
            int e  = idx >> 4;
            int tq = (idx & 15) << 2;
            float4 v4 = *(const float4*)(vbase + (size_t)e * T_ + kt0 + tq);
            vs[(tq + 0) * 128 + e] = v4.x;
            vs[(tq + 1) * 128 + e] = v4.y;
            vs[(tq + 2) * 128 + e] = v4.z;
            vs[(tq + 3) * 128 + e] = v4.w;
        }
        __syncthreads();

        // scores: s[4][4] = q[r0..][:] . k[c0..][:]
        float s[4][4];
#pragma unroll
        for (int i = 0; i < 4; i++)
#pragma unroll
            for (int j = 0; j < 4; j++) s[i][j] = 0.f;
#pragma unroll 8
        for (int d = 0; d < 64; d++) {
            float a0 = qs[(r0 + 0) * 65 + d];
            float a1 = qs[(r0 + 1) * 65 + d];
            float a2 = qs[(r0 + 2) * 65 + d];
            float a3 = qs[(r0 + 3) * 65 + d];
            float b0 = ks[(c0 + 0) * 65 + d];
            float b1 = ks[(c0 + 1) * 65 + d];
            float b2 = ks[(c0 + 2) * 65 + d];
            float b3 = ks[(c0 + 3) * 65 + d];
            s[0][0] += a0 * b0; s[0][1] += a0 * b1; s[0][2] += a0 * b2; s[0][3] += a0 * b3;
            s[1][0] += a1 * b0; s[1][1] += a1 * b1; s[1][2] += a1 * b2; s[1][3] += a1 * b3;
            s[2][0] += a2 * b0; s[2][1] += a2 * b1; s[2][2] += a2 * b2; s[2][3] += a2 * b3;
            s[3][0] += a3 * b0; s[3][1] += a3 * b1; s[3][2] += a3 * b2; s[3][3] += a3 * b3;
        }
#pragma unroll
        for (int i = 0; i < 4; i++)
#pragma unroll
            for (int j = 0; j < 4; j++)
                ps[(r0 + i) * 65 + c0 + j] = s[i][j] * SCALE_;
        __syncthreads();

        // online softmax stats: one thread per row
        if (tid < 64) {
            int r = tid;
            float mold = mrow[r];
            float tm = -1e30f;
#pragma unroll 8
            for (int c = 0; c < 64; c++) tm = fmaxf(tm, ps[r * 65 + c]);
            float mnew = fmaxf(mold, tm);
            float al = __expf(mold - mnew);
            float sum = 0.f;
#pragma unroll 8
            for (int c = 0; c < 64; c++) {
                float pv = __expf(ps[r * 65 + c] - mnew);
                ps[r * 65 + c] = pv;
                sum += pv;
            }
            lrow[r] = lrow[r] * al + sum;
            mrow[r] = mnew;
            arow[r] = al;
        }
        __syncthreads();

        // rescale accumulators and PV
        float al0 = arow[r0 + 0], al1 = arow[r0 + 1];
        float al2 = arow[r0 + 2], al3 = arow[r0 + 3];
#pragma unroll
        for (int j = 0; j < 8; j++) {
            acc[0][j] *= al0; acc[1][j] *= al1;
            acc[2][j] *= al2; acc[3][j] *= al3;
        }
#pragma unroll 4
        for (int c = 0; c < 64; c++) {
            float p0 = ps[(r0 + 0) * 65 + c];
            float p1 = ps[(r0 + 1) * 65 + c];
            float p2 = ps[(r0 + 2) * 65 + c];
            float p3 = ps[(r0 + 3) * 65 + c];
            float4 v0 = *(const float4*)(vs + c * 128 + e0);
            float4 v1 = *(const float4*)(vs + c * 128 + e0 + 4);
            acc[0][0] += p0 * v0.x; acc[0][1] += p0 * v0.y; acc[0][2] += p0 * v0.z; acc[0][3] += p0 * v0.w;
            acc[0][4] += p0 * v1.x; acc[0][5] += p0 * v1.y; acc[0][6] += p0 * v1.z; acc[0][7] += p0 * v1.w;
            acc[1][0] += p1 * v0.x; acc[1][1] += p1 * v0.y; acc[1][2] += p1 * v0.z; acc[1][3] += p1 * v0.w;
            acc[1][4] += p1 * v1.x; acc[1][5] += p1 * v1.y; acc[1][6] += p1 * v1.z; acc[1][7] += p1 * v1.w;
            acc[2][0] += p2 * v0.x; acc[2][1] += p2 * v0.y; acc[2][2] += p2 * v0.z; acc[2][3] += p2 * v0.w;
            acc[2][4] += p2 * v1.x; acc[2][5] += p2 * v1.y; acc[2][6] += p2 * v1.z; acc[2][7] += p2 * v1.w;
            acc[3][0] += p3 * v0.x; acc[3][1] += p3 * v0.y; acc[3][2] += p3 * v0.z; acc[3][3] += p3 * v0.w;
            acc[3][4] += p3 * v1.x; acc[3][5] += p3 * v1.y; acc[3][6] += p3 * v1.z; acc[3][7] += p3 * v1.w;
        }
        __syncthreads();
    }

    float* obase = g_att + ((size_t)(b * H_ + h) * T_ + qt * 64) * EV_;
#pragma unroll
    for (int i = 0; i < 4; i++) {
        float inv = 1.f / lrow[r0 + i];
        float4 o0 = {acc[i][0] * inv, acc[i][1] * inv, acc[i][2] * inv, acc[i][3] * inv};
        float4 o1 = {acc[i][4] * inv, acc[i][5] * inv, acc[i][6] * inv, acc[i][7] * inv};
        *(float4*)(obase + (size_t)(r0 + i) * EV_ + e0)     = o0;
        *(float4*)(obase + (size_t)(r0 + i) * EV_ + e0 + 4) = o1;
    }
}

// =============================================================================
// GEMM3: y[b,c,t] = x + b_out[c] + sum_e W_out[c,e] * u[b,e,t] * o[b,h(e),t,e%128]
// M=512 K=1024 N=1024
// =============================================================================
__global__ __launch_bounds__(256) void gemm_out_kernel(
    const float* __restrict__ W, const float* __restrict__ x,
    const float* __restrict__ bias)
{
    __shared__ __align__(16) float As[BKd * SPAD];
    __shared__ __align__(16) float Bs[BKd * SPAD];
    const int b   = blockIdx.z;
    const int m0  = blockIdx.y * BM;
    const int n0  = blockIdx.x * BN;
    const int tid = threadIdx.x;
    const int tm0 = (tid >> 4) << 3;
    const int tn0 = (tid & 15) << 3;
    const float* ub = g_uv + (size_t)b * 2 * E_ * T_;   // u = channels 0..1023
    const float* ob = g_att + (size_t)b * H_ * T_ * EV_;

    float acc[8][8];
#pragma unroll
    for (int i = 0; i < 8; i++)
#pragma unroll
        for (int j = 0; j < 8; j++) acc[i][j] = 0.f;

    for (int k0 = 0; k0 < E_; k0 += BKd) {
#pragma unroll
        for (int p = 0; p < 2; p++) {
            int idx = tid + 256 * p;
            int row = idx >> 2;
            int kq  = (idx & 3) << 2;
            float4 a4 = *(const float4*)(W + (size_t)(m0 + row) * E_ + k0 + kq);
            As[(kq + 0) * SPAD + row] = a4.x;
            As[(kq + 1) * SPAD + row] = a4.y;
            As[(kq + 2) * SPAD + row] = a4.z;
            As[(kq + 3) * SPAD + row] = a4.w;
        }
        // B tile: w[e,t] = u[e,t] * o[h(e), t, e%128]
#pragma unroll
        for (int p = 0; p < 2; p++) {
            int idx = tid + 256 * p;
            int n  = idx >> 2;          // 0..127 (t within tile)
            int kq = (idx & 3) << 2;    // 0,4,8,12
            int e  = k0 + kq;
            int hh = e >> 7;
            int eo = e & 127;
            float4 o4 = *(const float4*)(ob + ((size_t)hh * T_ + n0 + n) * EV_ + eo);
            const float* up = ub + (size_t)e * T_ + n0 + n;
            Bs[(kq + 0) * SPAD + n] = up[0]        * o4.x;
            Bs[(kq + 1) * SPAD + n] = up[T_]       * o4.y;
            Bs[(kq + 2) * SPAD + n] = up[2 * T_]   * o4.z;
            Bs[(kq + 3) * SPAD + n] = up[3 * T_]   * o4.w;
        }
        __syncthreads();
#pragma unroll
        for (int k = 0; k < BKd; k++) {
            float4 a0 = *(const float4*)(As + k * SPAD + tm0);
            float4 a1 = *(const float4*)(As + k * SPAD + tm0 + 4);
            float4 b0 = *(const float4*)(Bs + k * SPAD + tn0);
            float4 b1 = *(const float4*)(Bs + k * SPAD + tn0 + 4);
            float av[8] = {a0.x, a0.y, a0.z, a0.w, a1.x, a1.y, a1.z, a1.w};
            float bv[8] = {b0.x, b0.y, b0.z, b0.w, b1.x, b1.y, b1.z, b1.w};
#pragma unroll
            for (int i = 0; i < 8; i++)
#pragma unroll
                for (int j = 0; j < 8; j++) acc[i][j] += av[i] * bv[j];
        }
        __syncthreads();
    }

    const float* xb = x + (size_t)b * C_ * T_;
    float* yp = g_y + (size_t)b * C_ * T_;
#pragma unroll
    for (int i = 0; i < 8; i++) {
        int m = m0 + tm0 + i;
        float bo = bias[m];
        float4 x0 = *(const float4*)(xb + (size_t)m * T_ + n0 + tn0);
        float4 x1 = *(const float4*)(xb + (size_t)m * T_ + n0 + tn0 + 4);
        float4 y0 = {acc[i][0] + bo + x0.x, acc[i][1] + bo + x0.y,
                     acc[i][2] + bo + x0.z, acc[i][3] + bo + x0.w};
        float4 y1 = {acc[i][4] + bo + x1.x, acc[i][5] + bo + x1.y,
                     acc[i][6] + bo + x1.z, acc[i][7] + bo + x1.w};
        *(float4*)(yp + (size_t)m * T_ + n0 + tn0)     = y0;
        *(float4*)(yp + (size_t)m * T_ + n0 + tn0 + 4) = y1;
    }
}

// =============================================================================
// RMSNorm over C: out[b,c,t] = y * rsqrt(mean_c(y^2) + eps) * gamma[c]
// =============================================================================
__global__ __launch_bounds__(256) void rms_kernel(
    const float* __restrict__ gamma, float* __restrict__ out)
{
    const int b = blockIdx.y;
    const int t = blockIdx.x * 256 + threadIdx.x;
    const float* yb = g_y + (size_t)b * C_ * T_ + t;
    float ss = 0.f;
#pragma unroll 8
    for (int c = 0; c < C_; c++) {
        float v = yb[(size_t)c * T_];
        ss += v * v;
    }
    float r = rsqrtf(ss * (1.f / C_) + 1e-5f);
    float* obp = out + (size_t)b * C_ * T_ + t;
#pragma unroll 8
    for (int c = 0; c < C_; c++) {
        obp[(size_t)c * T_] = yb[(size_t)c * T_] * r * gamma[c];
    }
}

// =============================================================================
// launch
// =============================================================================
extern "C" void kernel_launch(void* const* d_in, const int* in_sizes, int n_in,
                              void* d_out, int out_size)
{
    const float* x      = (const float*)d_in[0];
    const float* W_in   = (const float*)d_in[1];
    const float* b_in   = (const float*)d_in[2];
    const float* W_attn = (const float*)d_in[3];
    const float* b_attn = (const float*)d_in[4];
    const float* w_q    = (const float*)d_in[5];
    const float* b_q    = (const float*)d_in[6];
    const float* w_k    = (const float*)d_in[7];
    const float* b_k    = (const float*)d_in[8];
    const float* W_out  = (const float*)d_in[9];
    const float* b_out  = (const float*)d_in[10];
    const float* gamma  = (const float*)d_in[11];
    float* out = (float*)d_out;

    cudaFuncSetAttribute(attn_kernel,
                         cudaFuncAttributeMaxDynamicSharedMemorySize,
                         ATTN_SMEM_BYTES);

    gemm_uv_kernel<<<dim3(T_ / BN, 2 * E_ / BM, B_), 256>>>(W_in, x, b_in);
    gemm_qk_kernel<<<dim3(T_ / BN, QK_ / BM, B_), 256>>>(W_attn, x, b_attn,
                                                         w_q, b_q, w_k, b_k);
    attn_kernel<<<dim3(T_ / 64, H_, B_), 256, ATTN_SMEM_BYTES>>>();
    gemm_out_kernel<<<dim3(T_ / BN, C_ / BM, B_), 256>>>(W_out, x, b_out);
    rms_kernel<<<dim3(T_ / 256, B_), 256>>>(gamma, out);
}

// round 2
// speedup vs baseline: 2.0883x; 2.0883x over previous
#include <cuda_runtime.h>
#include <math.h>

#define B_  8
#define C_  512
#define T_  1024
#define E_  1024
#define H_  8
#define HD_ 64
#define QK_ 512
#define EV_ 128

// scale = log(1024)/log(512)/sqrt(64) = (10/9)/8
#define SCALE_ 0.13888888888888889f

// ---------------- scratch (device globals) ------------
static __device__ float g_uv[(size_t)B_ * 2 * E_ * T_];   // u = o<1024, v = o>=1024
static __device__ float g_zq[(size_t)B_ * QK_ * T_];
static __device__ float g_zk[(size_t)B_ * QK_ * T_];
static __device__ float g_att[(size_t)B_ * H_ * T_ * EV_];// [b,h,t,e']
static __device__ float g_y[(size_t)B_ * C_ * T_];

// ---------------- tf32 MMA helper ----------------
__device__ __forceinline__ void mma_tf32(float& d0, float& d1, float& d2, float& d3,
                                         unsigned a0, unsigned a1, unsigned a2, unsigned a3,
                                         unsigned b0, unsigned b1)
{
    asm volatile(
        "mma.sync.aligned.m16n8k8.row.col.f32.tf32.tf32.f32 "
        "{%0,%1,%2,%3}, {%4,%5,%6,%7}, {%8,%9}, {%0,%1,%2,%3};\n"
        : "+f"(d0), "+f"(d1), "+f"(d2), "+f"(d3)
        : "r"(a0), "r"(a1), "r"(a2), "r"(a3), "r"(b0), "r"(b1));
}
__device__ __forceinline__ unsigned ldf(const float* p) {
    return __float_as_uint(*p);
}

// ---------------- GEMM tiling ----------------
#define BM 128
#define BN 128
#define BKd 16
#define SPAD 136   // stride giving conflict-free fragment loads (8*th4+g pattern)

// As: [k][m] transposed; Bs: [k][n]
#define GEMM_PROLOGUE()                                                        \
    __shared__ __align__(16) float As[BKd * SPAD];                             \
    __shared__ __align__(16) float Bs[BKd * SPAD];                             \
    const int b   = blockIdx.z;                                                \
    const int m0  = blockIdx.y * BM;                                           \
    const int n0  = blockIdx.x * BN;                                           \
    const int tid = threadIdx.x;                                               \
    const int lane = tid & 31, warp = tid >> 5;                                \
    const int g = lane >> 2, th4 = lane & 3;                                   \
    const int wm = (warp & 1) * 64, wn = (warp >> 1) * 32;                     \
    float acc[4][4][4];                                                        \
    _Pragma("unroll") for (int i = 0; i < 4; i++)                              \
    _Pragma("unroll") for (int j = 0; j < 4; j++)                              \
    _Pragma("unroll") for (int r = 0; r < 4; r++) acc[i][j][r] = 0.f;

#define GEMM_LOAD_A(W, ldk)                                                    \
    _Pragma("unroll") for (int p = 0; p < 2; p++) {                            \
        int idx = tid + 256 * p;                                               \
        int row = idx >> 2;                                                    \
        int kq  = (idx & 3) << 2;                                              \
        float4 a4 = *(const float4*)((W) + (size_t)(m0 + row) * (ldk) + k0 + kq);\
        As[(kq + 0) * SPAD + row] = a4.x;                                      \
        As[(kq + 1) * SPAD + row] = a4.y;                                      \
        As[(kq + 2) * SPAD + row] = a4.z;                                      \
        As[(kq + 3) * SPAD + row] = a4.w;                                      \
    }

#define GEMM_MAINCOMP()                                                        \
    _Pragma("unroll") for (int ks8 = 0; ks8 < 2; ks8++) {                      \
        const int kb = ks8 * 8;                                                \
        unsigned af[4][4];                                                     \
        _Pragma("unroll") for (int mi = 0; mi < 4; mi++) {                     \
            const int mr = wm + mi * 16 + g;                                   \
            af[mi][0] = ldf(As + (kb + th4) * SPAD + mr);                      \
            af[mi][1] = ldf(As + (kb + th4) * SPAD + mr + 8);                  \
            af[mi][2] = ldf(As + (kb + th4 + 4) * SPAD + mr);                  \
            af[mi][3] = ldf(As + (kb + th4 + 4) * SPAD + mr + 8);              \
        }                                                                      \
        unsigned bf[4][2];                                                     \
        _Pragma("unroll") for (int ni = 0; ni < 4; ni++) {                     \
            const int nc = wn + ni * 8 + g;                                    \
            bf[ni][0] = ldf(Bs + (kb + th4) * SPAD + nc);                      \
            bf[ni][1] = ldf(Bs + (kb + th4 + 4) * SPAD + nc);                  \
        }                                                                      \
        _Pragma("unroll") for (int mi = 0; mi < 4; mi++)                       \
        _Pragma("unroll") for (int ni = 0; ni < 4; ni++)                       \
            mma_tf32(acc[mi][ni][0], acc[mi][ni][1], acc[mi][ni][2], acc[mi][ni][3], \
                     af[mi][0], af[mi][1], af[mi][2], af[mi][3],               \
                     bf[ni][0], bf[ni][1]);                                    \
    }

// =============================================================================
// GEMM1: uv = silu(W_in @ x + b_in)   M=2048 K=512 N=1024
// =============================================================================
__global__ __launch_bounds__(256) void gemm_uv_mma(
    const float* __restrict__ W, const float* __restrict__ x,
    const float* __restrict__ bias)
{
    GEMM_PROLOGUE();
    const float* xb = x + (size_t)b * C_ * T_;
    for (int k0 = 0; k0 < C_; k0 += BKd) {
        GEMM_LOAD_A(W, C_);
#pragma unroll
        for (int p = 0; p < 2; p++) {
            int idx = tid + 256 * p;
            int kk  = idx >> 5;
            int nq  = (idx & 31) << 2;
            *(float4*)(Bs + kk * SPAD + nq) =
                *(const float4*)(xb + (size_t)(k0 + kk) * T_ + n0 + nq);
        }
        __syncthreads();
        GEMM_MAINCOMP();
        __syncthreads();
    }
    float* outp = g_uv + (size_t)b * 2 * E_ * T_;
#pragma unroll
    for (int mi = 0; mi < 4; mi++) {
        int m = m0 + wm + mi * 16 + g;
        float b0 = bias[m], b1 = bias[m + 8];
#pragma unroll
        for (int ni = 0; ni < 4; ni++) {
            int n = n0 + wn + ni * 8 + 2 * th4;
            float t0 = acc[mi][ni][0] + b0, t1 = acc[mi][ni][1] + b0;
            float t2 = acc[mi][ni][2] + b1, t3 = acc[mi][ni][3] + b1;
            float2 v0 = {t0 / (1.f + __expf(-t0)), t1 / (1.f + __expf(-t1))};
            float2 v1 = {t2 / (1.f + __expf(-t2)), t3 / (1.f + __expf(-t3))};
            *(float2*)(outp + (size_t)m * T_ + n)       = v0;
            *(float2*)(outp + (size_t)(m + 8) * T_ + n) = v1;
        }
    }
}

// =============================================================================
// GEMM2: z = W_attn @ x + b_attn; q = z*wq+bq; k = z*wk+bk   M=512 K=512
// =============================================================================
__global__ __launch_bounds__(256) void gemm_qk_mma(
    const float* __restrict__ W, const float* __restrict__ x,
    const float* __restrict__ bias,
    const float* __restrict__ wq, const float* __restrict__ bq,
    const float* __restrict__ wk, const float* __restrict__ bk)
{
    GEMM_PROLOGUE();
    const float* xb = x + (size_t)b * C_ * T_;
    for (int k0 = 0; k0 < C_; k0 += BKd) {
        GEMM_LOAD_A(W, C_);
#pragma unroll
        for (int p = 0; p < 2; p++) {
            int idx = tid + 256 * p;
            int kk  = idx >> 5;
            int nq  = (idx & 31) << 2;
            *(float4*)(Bs + kk * SPAD + nq) =
                *(const float4*)(xb + (size_t)(k0 + kk) * T_ + n0 + nq);
        }
        __syncthreads();
        GEMM_MAINCOMP();
        __syncthreads();
    }
    float* qp = g_zq + (size_t)b * QK_ * T_;
    float* kp = g_zk + (size_t)b * QK_ * T_;
#pragma unroll
    for (int mi = 0; mi < 4; mi++) {
        int m = m0 + wm + mi * 16 + g;
        float bi0 = bias[m], bi1 = bias[m + 8];
        float wq0 = wq[m], bq0 = bq[m], wk0 = wk[m], bk0 = bk[m];
        float wq1 = wq[m + 8], bq1 = bq[m + 8], wk1 = wk[m + 8], bk1 = bk[m + 8];
#pragma unroll
        for (int ni = 0; ni < 4; ni++) {
            int n = n0 + wn + ni * 8 + 2 * th4;
            float z0 = acc[mi][ni][0] + bi0, z1 = acc[mi][ni][1] + bi0;
            float z2 = acc[mi][ni][2] + bi1, z3 = acc[mi][ni][3] + bi1;
            float2 q0 = {z0 * wq0 + bq0, z1 * wq0 + bq0};
            float2 q1 = {z2 * wq1 + bq1, z3 * wq1 + bq1};
            float2 k0v = {z0 * wk0 + bk0, z1 * wk0 + bk0};
            float2 k1v = {z2 * wk1 + bk1, z3 * wk1 + bk1};
            *(float2*)(qp + (size_t)m * T_ + n)       = q0;
            *(float2*)(qp + (size_t)(m + 8) * T_ + n) = q1;
            *(float2*)(kp + (size_t)m * T_ + n)       = k0v;
            *(float2*)(kp + (size_t)(m + 8) * T_ + n) = k1v;
        }
    }
}

// =============================================================================
// Flash attention, tf32 mma. Block: 64 q rows, 4 warps (16 q rows/warp).
// =============================================================================
#define AQS 68
#define AVS 136
#define ATTN_SMEM_FLOATS (3 * 64 * AQS + 64 * AVS)
#define ATTN_SMEM_BYTES  (ATTN_SMEM_FLOATS * 4)

__global__ __launch_bounds__(128) void attn_mma_kernel()
{
    extern __shared__ __align__(16) float sm[];
    float* qs = sm;                       // [64][68]  (t, d), pre-scaled
    float* ks = sm + 64 * AQS;            // [64][68]  (t, d)
    float* vs = sm + 2 * 64 * AQS;        // [64][136] (t, e)
    float* ps = sm + 2 * 64 * AQS + 64 * AVS;  // [64][68] P tile

    const int b  = blockIdx.z;
    const int h  = blockIdx.y;
    const int qt = blockIdx.x;
    const int tid = threadIdx.x;
    const int lane = tid & 31, warp = tid >> 5;
    const int g = lane >> 2, th4 = lane & 3;
    const int wq = warp * 16;

    const float* qbase = g_zq + (size_t)(b * QK_ + h * HD_) * T_;
    const float* kbase = g_zk + (size_t)(b * QK_ + h * HD_) * T_;
    const float* vbase = g_uv + (size_t)(b * 2 * E_ + E_ + h * EV_) * T_;

    // load q tile transposed + pre-scale
#pragma unroll
    for (int p = 0; p < 8; p++) {
        int idx = tid + 128 * p;
        int d  = idx >> 4;
        int tq = (idx & 15) << 2;
        float4 q4 = *(const float4*)(qbase + (size_t)d * T_ + qt * 64 + tq);
        qs[(tq + 0) * AQS + d] = q4.x * SCALE_;
        qs[(tq + 1) * AQS + d] = q4.y * SCALE_;
        qs[(tq + 2) * AQS + d] = q4.z * SCALE_;
        qs[(tq + 3) * AQS + d] = q4.w * SCALE_;
    }

    float o[16][4];
#pragma unroll
    for (int e = 0; e < 16; e++)
#pragma unroll
        for (int r = 0; r < 4; r++) o[e][r] = 0.f;
    float m_0 = -1e30f, m_1 = -1e30f, l_0 = 0.f, l_1 = 0.f;

    __syncthreads();

    for (int kt = 0; kt < 16; kt++) {
        const int kt0 = kt * 64;
#pragma unroll
        for (int p = 0; p < 8; p++) {
            int idx = tid + 128 * p;
            int d  = idx >> 4;
            int tq = (idx & 15) << 2;
            float4 k4 = *(const float4*)(kbase + (size_t)d * T_ + kt0 + tq);
            ks[(tq + 0) * AQS + d] = k4.x;
            ks[(tq + 1) * AQS + d] = k4.y;
            ks[(tq + 2) * AQS + d] = k4.z;
            ks[(tq + 3) * AQS + d] = k4.w;
        }
#pragma unroll
        for (int p = 0; p < 16; p++) {
            int idx = tid + 128 * p;
            int e  = idx >> 4;
            int tq = (idx & 15) << 2;
            float4 v4 = *(const float4*)(vbase + (size_t)e * T_ + kt0 + tq);
            vs[(tq + 0) * AVS + e] = v4.x;
            vs[(tq + 1) * AVS + e] = v4.y;
            vs[(tq + 2) * AVS + e] = v4.z;
            vs[(tq + 3) * AVS + e] = v4.w;
        }
        __syncthreads();

        // ---- scores: S[16 q][64 kv] per warp ----
        float s[8][4];
#pragma unroll
        for (int ni = 0; ni < 8; ni++)
#pragma unroll
            for (int r = 0; r < 4; r++) s[ni][r] = 0.f;
#pragma unroll
        for (int kb8 = 0; kb8 < 8; kb8++) {
            const int kb = kb8 * 8;
            unsigned a0 = ldf(qs + (wq + g) * AQS + kb + th4);
            unsigned a1 = ldf(qs + (wq + g + 8) * AQS + kb + th4);
            unsigned a2 = ldf(qs + (wq + g) * AQS + kb + th4 + 4);
            unsigned a3 = ldf(qs + (wq + g + 8) * AQS + kb + th4 + 4);
#pragma unroll
            for (int ni = 0; ni < 8; ni++) {
                unsigned b0 = ldf(ks + (ni * 8 + g) * AQS + kb + th4);
                unsigned b1 = ldf(ks + (ni * 8 + g) * AQS + kb + th4 + 4);
                mma_tf32(s[ni][0], s[ni][1], s[ni][2], s[ni][3],
                         a0, a1, a2, a3, b0, b1);
            }
        }

        // ---- online softmax ----
        float tm0 = -1e30f, tm1 = -1e30f;
#pragma unroll
        for (int ni = 0; ni < 8; ni++) {
            tm0 = fmaxf(tm0, fmaxf(s[ni][0], s[ni][1]));
            tm1 = fmaxf(tm1, fmaxf(s[ni][2], s[ni][3]));
        }
        tm0 = fmaxf(tm0, __shfl_xor_sync(0xffffffffu, tm0, 1));
        tm0 = fmaxf(tm0, __shfl_xor_sync(0xffffffffu, tm0, 2));
        tm1 = fmaxf(tm1, __shfl_xor_sync(0xffffffffu, tm1, 1));
        tm1 = fmaxf(tm1, __shfl_xor_sync(0xffffffffu, tm1, 2));
        float mn0 = fmaxf(m_0, tm0), mn1 = fmaxf(m_1, tm1);
        float al0 = __expf(m_0 - mn0), al1 = __expf(m_1 - mn1);
        m_0 = mn0; m_1 = mn1;

        float rs0 = 0.f, rs1 = 0.f;
#pragma unroll
        for (int ni = 0; ni < 8; ni++) {
            float p0 = __expf(s[ni][0] - mn0);
            float p1 = __expf(s[ni][1] - mn0);
            float p2 = __expf(s[ni][2] - mn1);
            float p3 = __expf(s[ni][3] - mn1);
            rs0 += p0 + p1; rs1 += p2 + p3;
            float2 w0 = {p0, p1}, w1 = {p2, p3};
            *(float2*)(ps + (wq + g) * AQS + ni * 8 + 2 * th4)     = w0;
            *(float2*)(ps + (wq + g + 8) * AQS + ni * 8 + 2 * th4) = w1;
        }
        rs0 += __shfl_xor_sync(0xffffffffu, rs0, 1);
        rs0 += __shfl_xor_sync(0xffffffffu, rs0, 2);
        rs1 += __shfl_xor_sync(0xffffffffu, rs1, 1);
        rs1 += __shfl_xor_sync(0xffffffffu, rs1, 2);
        l_0 = l_0 * al0 + rs0;
        l_1 = l_1 * al1 + rs1;
        __syncwarp();

        // rescale O accumulators
#pragma unroll
        for (int e = 0; e < 16; e++) {
            o[e][0] *= al0; o[e][1] *= al0;
            o[e][2] *= al1; o[e][3] *= al1;
        }

        // ---- PV: O[16 q][128 e] += P[16 q][64 kv] @ V[64 kv][128 e] ----
#pragma unroll
        for (int kb8 = 0; kb8 < 8; kb8++) {
            const int kb = kb8 * 8;
            unsigned a0 = ldf(ps + (wq + g) * AQS + kb + th4);
            unsigned a1 = ldf(ps + (wq + g + 8) * AQS + kb + th4);
            unsigned a2 = ldf(ps + (wq + g) * AQS + kb + th4 + 4);
            unsigned a3 = ldf(ps + (wq + g + 8) * AQS + kb + th4 + 4);
#pragma unroll
            for (int et = 0; et < 16; et++) {
                unsigned b0 = ldf(vs + (kb + th4) * AVS + et * 8 + g);
                unsigned b1 = ldf(vs + (kb + th4 + 4) * AVS + et * 8 + g);
                mma_tf32(o[et][0], o[et][1], o[et][2], o[et][3],
                         a0, a1, a2, a3, b0, b1);
            }
        }
        __syncthreads();
    }

    float inv0 = 1.f / l_0, inv1 = 1.f / l_1;
    float* obase = g_att + ((size_t)(b * H_ + h) * T_ + qt * 64) * EV_;
#pragma unroll
    for (int et = 0; et < 16; et++) {
        int ec = et * 8 + 2 * th4;
        float2 w0 = {o[et][0] * inv0, o[et][1] * inv0};
        float2 w1 = {o[et][2] * inv1, o[et][3] * inv1};
        *(float2*)(obase + (size_t)(wq + g) * EV_ + ec)     = w0;
        *(float2*)(obase + (size_t)(wq + g + 8) * EV_ + ec) = w1;
    }
}

// =============================================================================
// GEMM3: y = x + b_out + W_out @ (u * o)   M=512 K=1024 N=1024
// =============================================================================
__global__ __launch_bounds__(256) void gemm_out_mma(
    const float* __restrict__ W, const float* __restrict__ x,
    const float* __restrict__ bias)
{
    GEMM_PROLOGUE();
    const float* ub = g_uv + (size_t)b * 2 * E_ * T_;
    const float* ob = g_att + (size_t)b * H_ * T_ * EV_;
    for (int k0 = 0; k0 < E_; k0 += BKd) {
        GEMM_LOAD_A(W, E_);
#pragma unroll
        for (int p = 0; p < 2; p++) {
            int idx = tid + 256 * p;
            int n  = idx >> 2;
            int kq = (idx & 3) << 2;
            int e  = k0 + kq;
            int hh = e >> 7;
            int eo = e & 127;
            float4 o4 = *(const float4*)(ob + ((size_t)hh * T_ + n0 + n) * EV_ + eo);
            const float* up = ub + (size_t)e * T_ + n0 + n;
            Bs[(kq + 0) * SPAD + n] = up[0]      * o4.x;
            Bs[(kq + 1) * SPAD + n] = up[T_]     * o4.y;
            Bs[(kq + 2) * SPAD + n] = up[2 * T_] * o4.z;
            Bs[(kq + 3) * SPAD + n] = up[3 * T_] * o4.w;
        }
        __syncthreads();
        GEMM_MAINCOMP();
        __syncthreads();
    }
    const float* xb = x + (size_t)b * C_ * T_;
    float* yp = g_y + (size_t)b * C_ * T_;
#pragma unroll
    for (int mi = 0; mi < 4; mi++) {
        int m = m0 + wm + mi * 16 + g;
        float bo0 = bias[m], bo1 = bias[m + 8];
#pragma unroll
        for (int ni = 0; ni < 4; ni++) {
            int n = n0 + wn + ni * 8 + 2 * th4;
            float2 x0 = *(const float2*)(xb + (size_t)m * T_ + n);
            float2 x1 = *(const float2*)(xb + (size_t)(m + 8) * T_ + n);
            float2 y0 = {acc[mi][ni][0] + bo0 + x0.x, acc[mi][ni][1] + bo0 + x0.y};
            float2 y1 = {acc[mi][ni][2] + bo1 + x1.x, acc[mi][ni][3] + bo1 + x1.y};
            *(float2*)(yp + (size_t)m * T_ + n)       = y0;
            *(float2*)(yp + (size_t)(m + 8) * T_ + n) = y1;
        }
    }
}

// =============================================================================
// RMSNorm over C
// =============================================================================
__global__ __launch_bounds__(256) void rms_kernel(
    const float* __restrict__ gamma, float* __restrict__ out)
{
    const int b = blockIdx.y;
    const int t = blockIdx.x * 256 + threadIdx.x;
    const float* yb = g_y + (size_t)b * C_ * T_ + t;
    float ss = 0.f;
#pragma unroll 8
    for (int c = 0; c < C_; c++) {
        float v = yb[(size_t)c * T_];
        ss += v * v;
    }
    float r = rsqrtf(ss * (1.f / C_) + 1e-5f);
    float* obp = out + (size_t)b * C_ * T_ + t;
#pragma unroll 8
    for (int c = 0; c < C_; c++) {
        obp[(size_t)c * T_] = yb[(size_t)c * T_] * r * gamma[c];
    }
}

// =============================================================================
// launch
// =============================================================================
extern "C" void kernel_launch(void* const* d_in, const int* in_sizes, int n_in,
                              void* d_out, int out_size)
{
    const float* x      = (const float*)d_in[0];
    const float* W_in   = (const float*)d_in[1];
    const float* b_in   = (const float*)d_in[2];
    const float* W_attn = (const float*)d_in[3];
    const float* b_attn = (const float*)d_in[4];
    const float* w_q    = (const float*)d_in[5];
    const float* b_q    = (const float*)d_in[6];
    const float* w_k    = (const float*)d_in[7];
    const float* b_k    = (const float*)d_in[8];
    const float* W_out  = (const float*)d_in[9];
    const float* b_out  = (const float*)d_in[10];
    const float* gamma  = (const float*)d_in[11];
    float* out = (float*)d_out;

    cudaFuncSetAttribute(attn_mma_kernel,
                         cudaFuncAttributeMaxDynamicSharedMemorySize,
                         ATTN_SMEM_BYTES);

    gemm_uv_mma<<<dim3(T_ / BN, 2 * E_ / BM, B_), 256>>>(W_in, x, b_in);
    gemm_qk_mma<<<dim3(T_ / BN, QK_ / BM, B_), 256>>>(W_attn, x, b_attn,
                                                      w_q, b_q, w_k, b_k);
    attn_mma_kernel<<<dim3(T_ / 64, H_, B_), 128, ATTN_SMEM_BYTES>>>();
    gemm_out_mma<<<dim3(T_ / BN, C_ / BM, B_), 256>>>(W_out, x, b_out);
    rms_kernel<<<dim3(T_ / 256, B_), 256>>>(gamma, out);
}

// round 3
// speedup vs baseline: 3.7047x; 1.7740x over previous
#include <cuda_runtime.h>
#include <cuda_bf16.h>
#include <math.h>

#define B_  8
#define C_  512
#define T_  1024
#define E_  1024
#define H_  8
#define HD_ 64
#define QK_ 512
#define EV_ 128

#define SCALE_ 0.13888888888888889f  // log(1024)/log(512)/sqrt(64)

// ---------------- scratch ----------------
static __device__ float g_uv[(size_t)B_ * 2 * E_ * T_];
static __device__ float g_zq[(size_t)B_ * QK_ * T_];
static __device__ float g_zk[(size_t)B_ * QK_ * T_];
static __device__ float g_att[(size_t)B_ * H_ * T_ * EV_];
static __device__ float g_y[(size_t)B_ * C_ * T_];

// ---------------- helpers ----------------
__device__ __forceinline__ unsigned packbf(float lo, float hi) {
    unsigned r;
    asm("cvt.rn.bf16x2.f32 %0, %1, %2;" : "=r"(r) : "f"(hi), "f"(lo));
    return r;
}
__device__ __forceinline__ void mma_bf16(float* d, const unsigned* a, const unsigned* b) {
    asm volatile(
        "mma.sync.aligned.m16n8k16.row.col.f32.bf16.bf16.f32 "
        "{%0,%1,%2,%3}, {%4,%5,%6,%7}, {%8,%9}, {%0,%1,%2,%3};"
        : "+f"(d[0]), "+f"(d[1]), "+f"(d[2]), "+f"(d[3])
        : "r"(a[0]), "r"(a[1]), "r"(a[2]), "r"(a[3]), "r"(b[0]), "r"(b[1]));
}
__device__ __forceinline__ void ldsm4(unsigned& r0, unsigned& r1, unsigned& r2, unsigned& r3,
                                      unsigned addr) {
    asm volatile("ldmatrix.sync.aligned.m8n8.x4.shared.b16 {%0,%1,%2,%3}, [%4];"
                 : "=r"(r0), "=r"(r1), "=r"(r2), "=r"(r3) : "r"(addr));
}
__device__ __forceinline__ void ldsm4t(unsigned& r0, unsigned& r1, unsigned& r2, unsigned& r3,
                                       unsigned addr) {
    asm volatile("ldmatrix.sync.aligned.m8n8.x4.trans.shared.b16 {%0,%1,%2,%3}, [%4];"
                 : "=r"(r0), "=r"(r1), "=r"(r2), "=r"(r3) : "r"(addr));
}

// ---------------- GEMM tiling: 128x128 CTA, BK=32, 8 warps (2x4) ----------------
#define ASTR 40    // bf16 stride of As rows (conflict-free ldmatrix)
#define BSTR 136   // bf16 stride of Bs rows

#define GEMM_DECL()                                                            \
    __shared__ __align__(16) unsigned short As[128 * ASTR];                    \
    __shared__ __align__(16) unsigned short Bs[32 * BSTR];                     \
    const int b   = blockIdx.z;                                                \
    const int m0  = blockIdx.y * 128;                                          \
    const int n0  = blockIdx.x * 128;                                          \
    const int tid = threadIdx.x;                                               \
    const int lane = tid & 31, warp = tid >> 5;                                \
    const int g = lane >> 2, th4 = lane & 3;                                   \
    const int wm = (warp & 1) * 64, wn = (warp >> 1) * 32;                     \
    const unsigned as_b = (unsigned)__cvta_generic_to_shared(As);              \
    const unsigned bs_b = (unsigned)__cvta_generic_to_shared(Bs);              \
    const unsigned a_addr0 = as_b + ((wm + (lane & 15)) * ASTR + (lane >> 4) * 8) * 2; \
    const unsigned b_addr0 = bs_b + ((lane & 15) * BSTR + wn + (lane >> 4) * 8) * 2;   \
    float acc[4][4][4];                                                        \
    _Pragma("unroll") for (int i = 0; i < 4; i++)                              \
    _Pragma("unroll") for (int j = 0; j < 4; j++)                              \
    _Pragma("unroll") for (int r = 0; r < 4; r++) acc[i][j][r] = 0.f;

#define GEMM_LDG_A(W, ldk, k0)                                                 \
    _Pragma("unroll") for (int p = 0; p < 4; p++) {                            \
        int idx = tid + 256 * p;                                               \
        ar[p] = *(const float4*)((W) + (size_t)(m0 + (idx >> 3)) * (ldk) + (k0) + (idx & 7) * 4); \
    }

#define GEMM_STS()                                                             \
    _Pragma("unroll") for (int p = 0; p < 4; p++) {                            \
        int idx = tid + 256 * p;                                               \
        uint2 wa = {packbf(ar[p].x, ar[p].y), packbf(ar[p].z, ar[p].w)};       \
        *(uint2*)&As[(idx >> 3) * ASTR + (idx & 7) * 4] = wa;                  \
        uint2 wb = {packbf(br[p].x, br[p].y), packbf(br[p].z, br[p].w)};       \
        *(uint2*)&Bs[(idx >> 5) * BSTR + (idx & 31) * 4] = wb;                 \
    }

#define GEMM_COMPUTE()                                                         \
    _Pragma("unroll") for (int ks16 = 0; ks16 < 2; ks16++) {                   \
        unsigned af[4][4], bf[4][2];                                           \
        _Pragma("unroll") for (int mi = 0; mi < 4; mi++)                       \
            ldsm4(af[mi][0], af[mi][1], af[mi][2], af[mi][3],                  \
                  a_addr0 + (mi * 16 * ASTR + ks16 * 16) * 2);                 \
        _Pragma("unroll") for (int nj = 0; nj < 2; nj++)                       \
            ldsm4t(bf[nj*2][0], bf[nj*2][1], bf[nj*2+1][0], bf[nj*2+1][1],     \
                   b_addr0 + (ks16 * 16 * BSTR + nj * 16) * 2);                \
        _Pragma("unroll") for (int mi = 0; mi < 4; mi++)                       \
        _Pragma("unroll") for (int ni = 0; ni < 4; ni++)                       \
            mma_bf16(acc[mi][ni], af[mi], bf[ni]);                             \
    }

// =============================================================================
// GEMM1: uv = silu(W_in @ x + b_in)   M=2048 K=512 N=1024
// =============================================================================
__global__ __launch_bounds__(256) void gemm_uv_bf16(
    const float* __restrict__ W, const float* __restrict__ x,
    const float* __restrict__ bias)
{
    GEMM_DECL();
    const float* xb = x + (size_t)b * C_ * T_;
    float4 ar[4], br[4];
    GEMM_LDG_A(W, C_, 0);
#pragma unroll
    for (int p = 0; p < 4; p++) {
        int idx = tid + 256 * p;
        br[p] = *(const float4*)(xb + (size_t)(idx >> 5) * T_ + n0 + (idx & 31) * 4);
    }
    for (int k0 = 0; k0 < C_; k0 += 32) {
        GEMM_STS();
        __syncthreads();
        if (k0 + 32 < C_) {
            GEMM_LDG_A(W, C_, k0 + 32);
#pragma unroll
            for (int p = 0; p < 4; p++) {
                int idx = tid + 256 * p;
                br[p] = *(const float4*)(xb + (size_t)(k0 + 32 + (idx >> 5)) * T_ + n0 + (idx & 31) * 4);
            }
        }
        GEMM_COMPUTE();
        __syncthreads();
    }
    float* outp = g_uv + (size_t)b * 2 * E_ * T_;
#pragma unroll
    for (int mi = 0; mi < 4; mi++) {
        int m = m0 + wm + mi * 16 + g;
        float b0 = bias[m], b1 = bias[m + 8];
#pragma unroll
        for (int ni = 0; ni < 4; ni++) {
            int n = n0 + wn + ni * 8 + 2 * th4;
            float t0 = acc[mi][ni][0] + b0, t1 = acc[mi][ni][1] + b0;
            float t2 = acc[mi][ni][2] + b1, t3 = acc[mi][ni][3] + b1;
            float2 v0 = {t0 / (1.f + __expf(-t0)), t1 / (1.f + __expf(-t1))};
            float2 v1 = {t2 / (1.f + __expf(-t2)), t3 / (1.f + __expf(-t3))};
            *(float2*)(outp + (size_t)m * T_ + n)       = v0;
            *(float2*)(outp + (size_t)(m + 8) * T_ + n) = v1;
        }
    }
}

// =============================================================================
// GEMM2: z = W_attn @ x + b_attn; q,k affine   M=512 K=512 N=1024
// =============================================================================
__global__ __launch_bounds__(256) void gemm_qk_bf16(
    const float* __restrict__ W, const float* __restrict__ x,
    const float* __restrict__ bias,
    const float* __restrict__ wq, const float* __restrict__ bq,
    const float* __restrict__ wk, const float* __restrict__ bk)
{
    GEMM_DECL();
    const float* xb = x + (size_t)b * C_ * T_;
    float4 ar[4], br[4];
    GEMM_LDG_A(W, C_, 0);
#pragma unroll
    for (int p = 0; p < 4; p++) {
        int idx = tid + 256 * p;
        br[p] = *(const float4*)(xb + (size_t)(idx >> 5) * T_ + n0 + (idx & 31) * 4);
    }
    for (int k0 = 0; k0 < C_; k0 += 32) {
        GEMM_STS();
        __syncthreads();
        if (k0 + 32 < C_) {
            GEMM_LDG_A(W, C_, k0 + 32);
#pragma unroll
            for (int p = 0; p < 4; p++) {
                int idx = tid + 256 * p;
                br[p] = *(const float4*)(xb + (size_t)(k0 + 32 + (idx >> 5)) * T_ + n0 + (idx & 31) * 4);
            }
        }
        GEMM_COMPUTE();
        __syncthreads();
    }
    float* qp = g_zq + (size_t)b * QK_ * T_;
    float* kp = g_zk + (size_t)b * QK_ * T_;
#pragma unroll
    for (int mi = 0; mi < 4; mi++) {
        int m = m0 + wm + mi * 16 + g;
        float bi0 = bias[m], bi1 = bias[m + 8];
        float wq0 = wq[m], bq0 = bq[m], wk0 = wk[m], bk0 = bk[m];
        float wq1 = wq[m + 8], bq1 = bq[m + 8], wk1 = wk[m + 8], bk1 = bk[m + 8];
#pragma unroll
        for (int ni = 0; ni < 4; ni++) {
            int n = n0 + wn + ni * 8 + 2 * th4;
            float z0 = acc[mi][ni][0] + bi0, z1 = acc[mi][ni][1] + bi0;
            float z2 = acc[mi][ni][2] + bi1, z3 = acc[mi][ni][3] + bi1;
            float2 q0 = {z0 * wq0 + bq0, z1 * wq0 + bq0};
            float2 q1 = {z2 * wq1 + bq1, z3 * wq1 + bq1};
            float2 k0v = {z0 * wk0 + bk0, z1 * wk0 + bk0};
            float2 k1v = {z2 * wk1 + bk1, z3 * wk1 + bk1};
            *(float2*)(qp + (size_t)m * T_ + n)       = q0;
            *(float2*)(qp + (size_t)(m + 8) * T_ + n) = q1;
            *(float2*)(kp + (size_t)m * T_ + n)       = k0v;
            *(float2*)(kp + (size_t)(m + 8) * T_ + n) = k1v;
        }
    }
}

// =============================================================================
// Flash attention bf16: BQ=64 (4 warps x 16 rows), BKV=64, register-resident P
// smem layouts (all bf16, natural orientation):
//   qs[d][q]  64x72, ks[d][kv] 64x72, vs[e][kv] 128x72
// =============================================================================
#define QSTR 72

__global__ __launch_bounds__(128) void attn_bf16_kernel()
{
    __shared__ __align__(16) unsigned short qs[64 * QSTR];
    __shared__ __align__(16) unsigned short ks[64 * QSTR];
    __shared__ __align__(16) unsigned short vs[128 * QSTR];

    const int b  = blockIdx.z;
    const int h  = blockIdx.y;
    const int qt = blockIdx.x;
    const int tid = threadIdx.x;
    const int lane = tid & 31, warp = tid >> 5;
    const int g = lane >> 2, th4 = lane & 3;
    const int wq = warp * 16;

    const float* qbase = g_zq + (size_t)(b * QK_ + h * HD_) * T_;
    const float* kbase = g_zk + (size_t)(b * QK_ + h * HD_) * T_;
    const float* vbase = g_uv + (size_t)(b * 2 * E_ + E_ + h * EV_) * T_;

    const unsigned qs_b = (unsigned)__cvta_generic_to_shared(qs);
    const unsigned ks_b = (unsigned)__cvta_generic_to_shared(ks);
    const unsigned vs_b = (unsigned)__cvta_generic_to_shared(vs);

    // ldmatrix lane base addresses
    // S A (trans from qs[d][q]): row = kd*16 + ((i>>4)<<3) + (i&7), col = wq + (i&8)
    const unsigned qa0 = qs_b + ((((lane >> 4) << 3) + (lane & 7)) * QSTR + wq + (lane & 8)) * 2;
    // S B (trans from ks[d][kv]): row = kd*16 + (i&7) + ((i>>3)&1)*8, col = kvj*16 + ((i>>4)&1)*8
    const unsigned ka0 = ks_b + (((lane & 7) + ((lane >> 3) & 1) * 8) * QSTR + ((lane >> 4) & 1) * 8) * 2;
    // PV B (non-trans from vs[e][kv]): row = ej*16 + (i&7) + ((i>>4)&1)*8, col = j*16 + (i&8)
    const unsigned va0 = vs_b + (((lane & 7) + ((lane >> 4) & 1) * 8) * QSTR + (lane & 8)) * 2;

    // load Q tile (pre-scaled) into qs[d][q]
#pragma unroll
    for (int p = 0; p < 4; p++) {
        int idx = tid + 128 * p;
        int d  = idx >> 3;
        int tq = (idx & 7) << 3;
        float4 q4 = *(const float4*)(qbase + (size_t)d * T_ + qt * 64 + tq);
        float4 q5 = *(const float4*)(qbase + (size_t)d * T_ + qt * 64 + tq + 4);
        uint4 w = {packbf(q4.x * SCALE_, q4.y * SCALE_), packbf(q4.z * SCALE_, q4.w * SCALE_),
                   packbf(q5.x * SCALE_, q5.y * SCALE_), packbf(q5.z * SCALE_, q5.w * SCALE_)};
        *(uint4*)&qs[d * QSTR + tq] = w;
    }

    float o[16][4];
#pragma unroll
    for (int e = 0; e < 16; e++)
#pragma unroll
        for (int r = 0; r < 4; r++) o[e][r] = 0.f;
    float m_0 = -1e30f, m_1 = -1e30f, l_0 = 0.f, l_1 = 0.f;

    for (int kt = 0; kt < 16; kt++) {
        const int kt0 = kt * 64;
        __syncthreads();
        // fill K: ks[d][kv], V: vs[e][kv]
#pragma unroll
        for (int p = 0; p < 4; p++) {
            int idx = tid + 128 * p;
            int d  = idx >> 3;
            int tq = (idx & 7) << 3;
            float4 k4 = *(const float4*)(kbase + (size_t)d * T_ + kt0 + tq);
            float4 k5 = *(const float4*)(kbase + (size_t)d * T_ + kt0 + tq + 4);
            uint4 w = {packbf(k4.x, k4.y), packbf(k4.z, k4.w),
                       packbf(k5.x, k5.y), packbf(k5.z, k5.w)};
            *(uint4*)&ks[d * QSTR + tq] = w;
        }
#pragma unroll
        for (int p = 0; p < 8; p++) {
            int idx = tid + 128 * p;
            int e  = idx >> 3;
            int tq = (idx & 7) << 3;
            float4 v4 = *(const float4*)(vbase + (size_t)e * T_ + kt0 + tq);
            float4 v5 = *(const float4*)(vbase + (size_t)e * T_ + kt0 + tq + 4);
            uint4 w = {packbf(v4.x, v4.y), packbf(v4.z, v4.w),
                       packbf(v5.x, v5.y), packbf(v5.z, v5.w)};
            *(uint4*)&vs[e * QSTR + tq] = w;
        }
        __syncthreads();

        // ---- S = Q K^T : per warp 16x64, k=64 in 4 k16 steps ----
        float s[8][4];
#pragma unroll
        for (int ni = 0; ni < 8; ni++)
#pragma unroll
            for (int r = 0; r < 4; r++) s[ni][r] = 0.f;
#pragma unroll
        for (int kd = 0; kd < 4; kd++) {
            unsigned a[4];
            ldsm4t(a[0], a[1], a[2], a[3], qa0 + kd * 16 * QSTR * 2);
#pragma unroll
            for (int kvj = 0; kvj < 4; kvj++) {
                unsigned r0, r1, r2, r3;
                ldsm4t(r0, r1, r2, r3, ka0 + (kd * 16 * QSTR + kvj * 16) * 2);
                unsigned b0[2] = {r0, r1}, b1[2] = {r2, r3};
                mma_bf16(s[2 * kvj],     a, b0);
                mma_bf16(s[2 * kvj + 1], a, b1);
            }
        }

        // ---- online softmax (rows g and g+8) ----
        float tm0 = -1e30f, tm1 = -1e30f;
#pragma unroll
        for (int ni = 0; ni < 8; ni++) {
            tm0 = fmaxf(tm0, fmaxf(s[ni][0], s[ni][1]));
            tm1 = fmaxf(tm1, fmaxf(s[ni][2], s[ni][3]));
        }
        tm0 = fmaxf(tm0, __shfl_xor_sync(0xffffffffu, tm0, 1));
        tm0 = fmaxf(tm0, __shfl_xor_sync(0xffffffffu, tm0, 2));
        tm1 = fmaxf(tm1, __shfl_xor_sync(0xffffffffu, tm1, 1));
        tm1 = fmaxf(tm1, __shfl_xor_sync(0xffffffffu, tm1, 2));
        float mn0 = fmaxf(m_0, tm0), mn1 = fmaxf(m_1, tm1);
        float al0 = __expf(m_0 - mn0), al1 = __expf(m_1 - mn1);
        m_0 = mn0; m_1 = mn1;

        float rs0 = 0.f, rs1 = 0.f;
#pragma unroll
        for (int ni = 0; ni < 8; ni++) {
            s[ni][0] = __expf(s[ni][0] - mn0);
            s[ni][1] = __expf(s[ni][1] - mn0);
            s[ni][2] = __expf(s[ni][2] - mn1);
            s[ni][3] = __expf(s[ni][3] - mn1);
            rs0 += s[ni][0] + s[ni][1];
            rs1 += s[ni][2] + s[ni][3];
        }
        rs0 += __shfl_xor_sync(0xffffffffu, rs0, 1);
        rs0 += __shfl_xor_sync(0xffffffffu, rs0, 2);
        rs1 += __shfl_xor_sync(0xffffffffu, rs1, 1);
        rs1 += __shfl_xor_sync(0xffffffffu, rs1, 2);
        l_0 = l_0 * al0 + rs0;
        l_1 = l_1 * al1 + rs1;

        // P -> bf16 A fragments (register resident)
        unsigned pf[4][4];
#pragma unroll
        for (int j = 0; j < 4; j++) {
            pf[j][0] = packbf(s[2 * j][0],     s[2 * j][1]);
            pf[j][1] = packbf(s[2 * j][2],     s[2 * j][3]);
            pf[j][2] = packbf(s[2 * j + 1][0], s[2 * j + 1][1]);
            pf[j][3] = packbf(s[2 * j + 1][2], s[2 * j + 1][3]);
        }

        // rescale O
#pragma unroll
        for (int e = 0; e < 16; e++) {
            o[e][0] *= al0; o[e][1] *= al0;
            o[e][2] *= al1; o[e][3] *= al1;
        }

        // ---- O += P V : n=128 (16 e-blocks), k=64 (4 k16) ----
#pragma unroll
        for (int j = 0; j < 4; j++) {
#pragma unroll
            for (int ej = 0; ej < 8; ej++) {
                unsigned r0, r1, r2, r3;
                ldsm4(r0, r1, r2, r3, va0 + (ej * 16 * QSTR + j * 16) * 2);
                unsigned b0[2] = {r0, r1}, b1[2] = {r2, r3};
                mma_bf16(o[2 * ej],     pf[j], b0);
                mma_bf16(o[2 * ej + 1], pf[j], b1);
            }
        }
    }

    float inv0 = 1.f / l_0, inv1 = 1.f / l_1;
    float* obase = g_att + ((size_t)(b * H_ + h) * T_ + qt * 64) * EV_;
#pragma unroll
    for (int et = 0; et < 16; et++) {
        int ec = et * 8 + 2 * th4;
        float2 w0 = {o[et][0] * inv0, o[et][1] * inv0};
        float2 w1 = {o[et][2] * inv1, o[et][3] * inv1};
        *(float2*)(obase + (size_t)(wq + g) * EV_ + ec)     = w0;
        *(float2*)(obase + (size_t)(wq + g + 8) * EV_ + ec) = w1;
    }
}

// =============================================================================
// GEMM3: y = x + b_out + W_out @ (u * o)   M=512 K=1024 N=1024
// =============================================================================
__global__ __launch_bounds__(256) void gemm_out_bf16(
    const float* __restrict__ W, const float* __restrict__ x,
    const float* __restrict__ bias)
{
    GEMM_DECL();
    const float* ub = g_uv + (size_t)b * 2 * E_ * T_;
    const float* ob = g_att + (size_t)b * H_ * T_ * EV_;
    float4 ar[4], br[4], orr[4];

#define LDG_B3(k0)                                                             \
    _Pragma("unroll") for (int p = 0; p < 4; p++) {                            \
        int idx = tid + 256 * p;                                               \
        int e  = (k0) + (idx >> 5);                                            \
        int nq = n0 + (idx & 31) * 4;                                          \
        br[p] = *(const float4*)(ub + (size_t)e * T_ + nq);                    \
        int hh = e >> 7, eo = e & 127;                                         \
        const float* op = ob + ((size_t)hh * T_ + nq) * EV_ + eo;              \
        orr[p].x = op[0]; orr[p].y = op[EV_]; orr[p].z = op[2 * EV_]; orr[p].w = op[3 * EV_]; \
    }

    GEMM_LDG_A(W, E_, 0);
    LDG_B3(0);
    for (int k0 = 0; k0 < E_; k0 += 32) {
#pragma unroll
        for (int p = 0; p < 4; p++) {
            int idx = tid + 256 * p;
            uint2 wa = {packbf(ar[p].x, ar[p].y), packbf(ar[p].z, ar[p].w)};
            *(uint2*)&As[(idx >> 3) * ASTR + (idx & 7) * 4] = wa;
            uint2 wb = {packbf(br[p].x * orr[p].x, br[p].y * orr[p].y),
                        packbf(br[p].z * orr[p].z, br[p].w * orr[p].w)};
            *(uint2*)&Bs[(idx >> 5) * BSTR + (idx & 31) * 4] = wb;
        }
        __syncthreads();
        if (k0 + 32 < E_) {
            GEMM_LDG_A(W, E_, k0 + 32);
            LDG_B3(k0 + 32);
        }
        GEMM_COMPUTE();
        __syncthreads();
    }
    const float* xb = x + (size_t)b * C_ * T_;
    float* yp = g_y + (size_t)b * C_ * T_;
#pragma unroll
    for (int mi = 0; mi < 4; mi++) {
        int m = m0 + wm + mi * 16 + g;
        float bo0 = bias[m], bo1 = bias[m + 8];
#pragma unroll
        for (int ni = 0; ni < 4; ni++) {
            int n = n0 + wn + ni * 8 + 2 * th4;
            float2 x0 = *(const float2*)(xb + (size_t)m * T_ + n);
            float2 x1 = *(const float2*)(xb + (size_t)(m + 8) * T_ + n);
            float2 y0 = {acc[mi][ni][0] + bo0 + x0.x, acc[mi][ni][1] + bo0 + x0.y};
            float2 y1 = {acc[mi][ni][2] + bo1 + x1.x, acc[mi][ni][3] + bo1 + x1.y};
            *(float2*)(yp + (size_t)m * T_ + n)       = y0;
            *(float2*)(yp + (size_t)(m + 8) * T_ + n) = y1;
        }
    }
}

// =============================================================================
// RMSNorm over C (256 blocks: 32 t-cols x 8 c-segments per block)
// =============================================================================
__global__ __launch_bounds__(256) void rms2_kernel(
    const float* __restrict__ gamma, float* __restrict__ out)
{
    __shared__ float red[8][32];
    __shared__ float rbuf[32];
    const int b = blockIdx.y;
    const int tseg = threadIdx.x & 31, cseg = threadIdx.x >> 5;
    const int t = blockIdx.x * 32 + tseg;
    const float* yb = g_y + (size_t)b * C_ * T_ + t;
    float ss = 0.f;
#pragma unroll 8
    for (int c = cseg * 64; c < cseg * 64 + 64; c++) {
        float v = yb[(size_t)c * T_];
        ss += v * v;
    }
    red[cseg][tseg] = ss;
    __syncthreads();
    if (cseg == 0) {
        float tot = 0.f;
#pragma unroll
        for (int i = 0; i < 8; i++) tot += red[i][tseg];
        rbuf[tseg] = rsqrtf(tot * (1.f / C_) + 1e-5f);
    }
    __syncthreads();
    float r = rbuf[tseg];
    float* op = out + (size_t)b * C_ * T_ + t;
#pragma unroll 8
    for (int c = cseg * 64; c < cseg * 64 + 64; c++) {
        op[(size_t)c * T_] = yb[(size_t)c * T_] * r * gamma[c];
    }
}

// =============================================================================
// launch
// =============================================================================
extern "C" void kernel_launch(void* const* d_in, const int* in_sizes, int n_in,
                              void* d_out, int out_size)
{
    const float* x      = (const float*)d_in[0];
    const float* W_in   = (const float*)d_in[1];
    const float* b_in   = (const float*)d_in[2];
    const float* W_attn = (const float*)d_in[3];
    const float* b_attn = (const float*)d_in[4];
    const float* w_q    = (const float*)d_in[5];
    const float* b_q    = (const float*)d_in[6];
    const float* w_k    = (const float*)d_in[7];
    const float* b_k    = (const float*)d_in[8];
    const float* W_out  = (const float*)d_in[9];
    const float* b_out  = (const float*)d_in[10];
    const float* gamma  = (const float*)d_in[11];
    float* out = (float*)d_out;

    gemm_uv_bf16<<<dim3(T_ / 128, 2 * E_ / 128, B_), 256>>>(W_in, x, b_in);
    gemm_qk_bf16<<<dim3(T_ / 128, QK_ / 128, B_), 256>>>(W_attn, x, b_attn,
                                                         w_q, b_q, w_k, b_k);
    attn_bf16_kernel<<<dim3(T_ / 64, H_, B_), 128>>>();
    gemm_out_bf16<<<dim3(T_ / 128, C_ / 128, B_), 256>>>(W_out, x, b_out);
    rms2_kernel<<<dim3(T_ / 32, B_), 256>>>(gamma, out);
}

// round 4
// speedup vs baseline: 5.3067x; 1.4324x over previous
#include <cuda_runtime.h>
#include <cuda_bf16.h>
#include <math.h>

#define B_  8
#define C_  512
#define T_  1024
#define E_  1024
#define H_  8
#define HD_ 64
#define QK_ 512
#define EV_ 128

#define SCALE_ 0.13888888888888889f  // log(1024)/log(512)/sqrt(64)

// ---------------- scratch ----------------
static __device__ float g_uv[(size_t)B_ * 2 * E_ * T_];
static __device__ float g_zq[(size_t)B_ * QK_ * T_];
static __device__ float g_zk[(size_t)B_ * QK_ * T_];
static __device__ __nv_bfloat16 g_w[(size_t)B_ * E_ * T_];   // u * o / l, [b,e,t]
static __device__ float g_y[(size_t)B_ * C_ * T_];

// ---------------- helpers ----------------
__device__ __forceinline__ unsigned packbf(float lo, float hi) {
    unsigned r;
    asm("cvt.rn.bf16x2.f32 %0, %1, %2;" : "=r"(r) : "f"(hi), "f"(lo));
    return r;
}
__device__ __forceinline__ void mma_bf16(float* d, const unsigned* a, const unsigned* b) {
    asm volatile(
        "mma.sync.aligned.m16n8k16.row.col.f32.bf16.bf16.f32 "
        "{%0,%1,%2,%3}, {%4,%5,%6,%7}, {%8,%9}, {%0,%1,%2,%3};"
        : "+f"(d[0]), "+f"(d[1]), "+f"(d[2]), "+f"(d[3])
        : "r"(a[0]), "r"(a[1]), "r"(a[2]), "r"(a[3]), "r"(b[0]), "r"(b[1]));
}
__device__ __forceinline__ void ldsm4(unsigned& r0, unsigned& r1, unsigned& r2, unsigned& r3,
                                      unsigned addr) {
    asm volatile("ldmatrix.sync.aligned.m8n8.x4.shared.b16 {%0,%1,%2,%3}, [%4];"
                 : "=r"(r0), "=r"(r1), "=r"(r2), "=r"(r3) : "r"(addr));
}
__device__ __forceinline__ void ldsm4t(unsigned& r0, unsigned& r1, unsigned& r2, unsigned& r3,
                                       unsigned addr) {
    asm volatile("ldmatrix.sync.aligned.m8n8.x4.trans.shared.b16 {%0,%1,%2,%3}, [%4];"
                 : "=r"(r0), "=r"(r1), "=r"(r2), "=r"(r3) : "r"(addr));
}

// ---------------- GEMM tiling: 128x128 CTA, BK=32, 8 warps (2x4) ----------------
#define ASTR 40
#define BSTR 136

#define GEMM_DECL()                                                            \
    __shared__ __align__(16) unsigned short As[128 * ASTR];                    \
    __shared__ __align__(16) unsigned short Bs[32 * BSTR];                     \
    const int b   = blockIdx.z;                                                \
    const int m0  = blockIdx.y * 128;                                          \
    const int n0  = blockIdx.x * 128;                                          \
    const int tid = threadIdx.x;                                               \
    const int lane = tid & 31, warp = tid >> 5;                                \
    const int g = lane >> 2, th4 = lane & 3;                                   \
    const int wm = (warp & 1) * 64, wn = (warp >> 1) * 32;                     \
    const unsigned as_b = (unsigned)__cvta_generic_to_shared(As);              \
    const unsigned bs_b = (unsigned)__cvta_generic_to_shared(Bs);              \
    const unsigned a_addr0 = as_b + ((wm + (lane & 15)) * ASTR + (lane >> 4) * 8) * 2; \
    const unsigned b_addr0 = bs_b + ((lane & 15) * BSTR + wn + (lane >> 4) * 8) * 2;   \
    float acc[4][4][4];                                                        \
    _Pragma("unroll") for (int i = 0; i < 4; i++)                              \
    _Pragma("unroll") for (int j = 0; j < 4; j++)                              \
    _Pragma("unroll") for (int r = 0; r < 4; r++) acc[i][j][r] = 0.f;

#define GEMM_LDG_A(W, ldk, k0)                                                 \
    _Pragma("unroll") for (int p = 0; p < 4; p++) {                            \
        int idx = tid + 256 * p;                                               \
        ar[p] = *(const float4*)((W) + (size_t)(m0 + (idx >> 3)) * (ldk) + (k0) + (idx & 7) * 4); \
    }

#define GEMM_STS()                                                             \
    _Pragma("unroll") for (int p = 0; p < 4; p++) {                            \
        int idx = tid + 256 * p;                                               \
        uint2 wa = {packbf(ar[p].x, ar[p].y), packbf(ar[p].z, ar[p].w)};       \
        *(uint2*)&As[(idx >> 3) * ASTR + (idx & 7) * 4] = wa;                  \
        uint2 wb = {packbf(br[p].x, br[p].y), packbf(br[p].z, br[p].w)};       \
        *(uint2*)&Bs[(idx >> 5) * BSTR + (idx & 31) * 4] = wb;                 \
    }

#define GEMM_COMPUTE()                                                         \
    _Pragma("unroll") for (int ks16 = 0; ks16 < 2; ks16++) {                   \
        unsigned af[4][4], bf[4][2];                                           \
        _Pragma("unroll") for (int mi = 0; mi < 4; mi++)                       \
            ldsm4(af[mi][0], af[mi][1], af[mi][2], af[mi][3],                  \
                  a_addr0 + (mi * 16 * ASTR + ks16 * 16) * 2);                 \
        _Pragma("unroll") for (int nj = 0; nj < 2; nj++)                       \
            ldsm4t(bf[nj*2][0], bf[nj*2][1], bf[nj*2+1][0], bf[nj*2+1][1],     \
                   b_addr0 + (ks16 * 16 * BSTR + nj * 16) * 2);                \
        _Pragma("unroll") for (int mi = 0; mi < 4; mi++)                       \
        _Pragma("unroll") for (int ni = 0; ni < 4; ni++)                       \
            mma_bf16(acc[mi][ni], af[mi], bf[ni]);                             \
    }

// =============================================================================
// GEMM1: uv = silu(W_in @ x + b_in)   M=2048 K=512 N=1024
// =============================================================================
__global__ __launch_bounds__(256) void gemm_uv_bf16(
    const float* __restrict__ W, const float* __restrict__ x,
    const float* __restrict__ bias)
{
    GEMM_DECL();
    const float* xb = x + (size_t)b * C_ * T_;
    float4 ar[4], br[4];
    GEMM_LDG_A(W, C_, 0);
#pragma unroll
    for (int p = 0; p < 4; p++) {
        int idx = tid + 256 * p;
        br[p] = *(const float4*)(xb + (size_t)(idx >> 5) * T_ + n0 + (idx & 31) * 4);
    }
    for (int k0 = 0; k0 < C_; k0 += 32) {
        GEMM_STS();
        __syncthreads();
        if (k0 + 32 < C_) {
            GEMM_LDG_A(W, C_, k0 + 32);
#pragma unroll
            for (int p = 0; p < 4; p++) {
                int idx = tid + 256 * p;
                br[p] = *(const float4*)(xb + (size_t)(k0 + 32 + (idx >> 5)) * T_ + n0 + (idx & 31) * 4);
            }
        }
        GEMM_COMPUTE();
        __syncthreads();
    }
    float* outp = g_uv + (size_t)b * 2 * E_ * T_;
#pragma unroll
    for (int mi = 0; mi < 4; mi++) {
        int m = m0 + wm + mi * 16 + g;
        float b0 = bias[m], b1 = bias[m + 8];
#pragma unroll
        for (int ni = 0; ni < 4; ni++) {
            int n = n0 + wn + ni * 8 + 2 * th4;
            float t0 = acc[mi][ni][0] + b0, t1 = acc[mi][ni][1] + b0;
            float t2 = acc[mi][ni][2] + b1, t3 = acc[mi][ni][3] + b1;
            float2 v0 = {t0 / (1.f + __expf(-t0)), t1 / (1.f + __expf(-t1))};
            float2 v1 = {t2 / (1.f + __expf(-t2)), t3 / (1.f + __expf(-t3))};
            *(float2*)(outp + (size_t)m * T_ + n)       = v0;
            *(float2*)(outp + (size_t)(m + 8) * T_ + n) = v1;
        }
    }
}

// =============================================================================
// GEMM2: z = W_attn @ x + b_attn; q,k affine   M=512 K=512 N=1024
// =============================================================================
__global__ __launch_bounds__(256) void gemm_qk_bf16(
    const float* __restrict__ W, const float* __restrict__ x,
    const float* __restrict__ bias,
    const float* __restrict__ wq, const float* __restrict__ bq,
    const float* __restrict__ wk, const float* __restrict__ bk)
{
    GEMM_DECL();
    const float* xb = x + (size_t)b * C_ * T_;
    float4 ar[4], br[4];
    GEMM_LDG_A(W, C_, 0);
#pragma unroll
    for (int p = 0; p < 4; p++) {
        int idx = tid + 256 * p;
        br[p] = *(const float4*)(xb + (size_t)(idx >> 5) * T_ + n0 + (idx & 31) * 4);
    }
    for (int k0 = 0; k0 < C_; k0 += 32) {
        GEMM_STS();
        __syncthreads();
        if (k0 + 32 < C_) {
            GEMM_LDG_A(W, C_, k0 + 32);
#pragma unroll
            for (int p = 0; p < 4; p++) {
                int idx = tid + 256 * p;
                br[p] = *(const float4*)(xb + (size_t)(k0 + 32 + (idx >> 5)) * T_ + n0 + (idx & 31) * 4);
            }
        }
        GEMM_COMPUTE();
        __syncthreads();
    }
    float* qp = g_zq + (size_t)b * QK_ * T_;
    float* kp = g_zk + (size_t)b * QK_ * T_;
#pragma unroll
    for (int mi = 0; mi < 4; mi++) {
        int m = m0 + wm + mi * 16 + g;
        float bi0 = bias[m], bi1 = bias[m + 8];
        float wq0 = wq[m], bq0 = bq[m], wk0 = wk[m], bk0 = bk[m];
        float wq1 = wq[m + 8], bq1 = bq[m + 8], wk1 = wk[m + 8], bk1 = bk[m + 8];
#pragma unroll
        for (int ni = 0; ni < 4; ni++) {
            int n = n0 + wn + ni * 8 + 2 * th4;
            float z0 = acc[mi][ni][0] + bi0, z1 = acc[mi][ni][1] + bi0;
            float z2 = acc[mi][ni][2] + bi1, z3 = acc[mi][ni][3] + bi1;
            float2 q0 = {z0 * wq0 + bq0, z1 * wq0 + bq0};
            float2 q1 = {z2 * wq1 + bq1, z3 * wq1 + bq1};
            float2 k0v = {z0 * wk0 + bk0, z1 * wk0 + bk0};
            float2 k1v = {z2 * wk1 + bk1, z3 * wk1 + bk1};
            *(float2*)(qp + (size_t)m * T_ + n)       = q0;
            *(float2*)(qp + (size_t)(m + 8) * T_ + n) = q1;
            *(float2*)(kp + (size_t)m * T_ + n)       = k0v;
            *(float2*)(kp + (size_t)(m + 8) * T_ + n) = k1v;
        }
    }
}

// =============================================================================
// Flash attention bf16 + fused u-gating epilogue.
// BQ=64 (4 warps x 16 rows), BKV=64, register-resident P.
// Epilogue: o fragments -> smem [e][t] -> w = u*o/l -> g_w[b,e,t] bf16 coalesced.
// =============================================================================
#define QSTR 72
#define OSTR 68

__global__ __launch_bounds__(128) void attn_bf16_kernel()
{
    __shared__ __align__(16) char smbuf[(64 * QSTR + 64 * QSTR + 128 * QSTR) * 2];
    __shared__ float linv[64];
    unsigned short* qs = (unsigned short*)smbuf;
    unsigned short* ks = qs + 64 * QSTR;
    unsigned short* vs = ks + 64 * QSTR;
    float* os = (float*)smbuf;   // 128*68*4 = 34816 <= 36864

    const int b  = blockIdx.z;
    const int h  = blockIdx.y;
    const int qt = blockIdx.x;
    const int tid = threadIdx.x;
    const int lane = tid & 31, warp = tid >> 5;
    const int g = lane >> 2, th4 = lane & 3;
    const int wq = warp * 16;

    const float* qbase = g_zq + (size_t)(b * QK_ + h * HD_) * T_;
    const float* kbase = g_zk + (size_t)(b * QK_ + h * HD_) * T_;
    const float* vbase = g_uv + (size_t)(b * 2 * E_ + E_ + h * EV_) * T_;

    const unsigned qs_b = (unsigned)__cvta_generic_to_shared(qs);
    const unsigned ks_b = (unsigned)__cvta_generic_to_shared(ks);
    const unsigned vs_b = (unsigned)__cvta_generic_to_shared(vs);

    const unsigned qa0 = qs_b + ((((lane >> 4) << 3) + (lane & 7)) * QSTR + wq + (lane & 8)) * 2;
    const unsigned ka0 = ks_b + (((lane & 7) + ((lane >> 3) & 1) * 8) * QSTR + ((lane >> 4) & 1) * 8) * 2;
    const unsigned va0 = vs_b + (((lane & 7) + ((lane >> 4) & 1) * 8) * QSTR + (lane & 8)) * 2;

#pragma unroll
    for (int p = 0; p < 4; p++) {
        int idx = tid + 128 * p;
        int d  = idx >> 3;
        int tq = (idx & 7) << 3;
        float4 q4 = *(const float4*)(qbase + (size_t)d * T_ + qt * 64 + tq);
        float4 q5 = *(const float4*)(qbase + (size_t)d * T_ + qt * 64 + tq + 4);
        uint4 w = {packbf(q4.x * SCALE_, q4.y * SCALE_), packbf(q4.z * SCALE_, q4.w * SCALE_),
                   packbf(q5.x * SCALE_, q5.y * SCALE_), packbf(q5.z * SCALE_, q5.w * SCALE_)};
        *(uint4*)&qs[d * QSTR + tq] = w;
    }

    float o[16][4];
#pragma unroll
    for (int e = 0; e < 16; e++)
#pragma unroll
        for (int r = 0; r < 4; r++) o[e][r] = 0.f;
    float m_0 = -1e30f, m_1 = -1e30f, l_0 = 0.f, l_1 = 0.f;

    for (int kt = 0; kt < 16; kt++) {
        const int kt0 = kt * 64;
        __syncthreads();
#pragma unroll
        for (int p = 0; p < 4; p++) {
            int idx = tid + 128 * p;
            int d  = idx >> 3;
            int tq = (idx & 7) << 3;
            float4 k4 = *(const float4*)(kbase + (size_t)d * T_ + kt0 + tq);
            float4 k5 = *(const float4*)(kbase + (size_t)d * T_ + kt0 + tq + 4);
            uint4 w = {packbf(k4.x, k4.y), packbf(k4.z, k4.w),
                       packbf(k5.x, k5.y), packbf(k5.z, k5.w)};
            *(uint4*)&ks[d * QSTR + tq] = w;
        }
#pragma unroll
        for (int p = 0; p < 8; p++) {
            int idx = tid + 128 * p;
            int e  = idx >> 3;
            int tq = (idx & 7) << 3;
            float4 v4 = *(const float4*)(vbase + (size_t)e * T_ + kt0 + tq);
            float4 v5 = *(const float4*)(vbase + (size_t)e * T_ + kt0 + tq + 4);
            uint4 w = {packbf(v4.x, v4.y), packbf(v4.z, v4.w),
                       packbf(v5.x, v5.y), packbf(v5.z, v5.w)};
            *(uint4*)&vs[e * QSTR + tq] = w;
        }
        __syncthreads();

        float s[8][4];
#pragma unroll
        for (int ni = 0; ni < 8; ni++)
#pragma unroll
            for (int r = 0; r < 4; r++) s[ni][r] = 0.f;
#pragma unroll
        for (int kd = 0; kd < 4; kd++) {
            unsigned a[4];
            ldsm4t(a[0], a[1], a[2], a[3], qa0 + kd * 16 * QSTR * 2);
#pragma unroll
            for (int kvj = 0; kvj < 4; kvj++) {
                unsigned r0, r1, r2, r3;
                ldsm4t(r0, r1, r2, r3, ka0 + (kd * 16 * QSTR + kvj * 16) * 2);
                unsigned b0[2] = {r0, r1}, b1[2] = {r2, r3};
                mma_bf16(s[2 * kvj],     a, b0);
                mma_bf16(s[2 * kvj + 1], a, b1);
            }
        }

        float tm0 = -1e30f, tm1 = -1e30f;
#pragma unroll
        for (int ni = 0; ni < 8; ni++) {
            tm0 = fmaxf(tm0, fmaxf(s[ni][0], s[ni][1]));
            tm1 = fmaxf(tm1, fmaxf(s[ni][2], s[ni][3]));
        }
        tm0 = fmaxf(tm0, __shfl_xor_sync(0xffffffffu, tm0, 1));
        tm0 = fmaxf(tm0, __shfl_xor_sync(0xffffffffu, tm0, 2));
        tm1 = fmaxf(tm1, __shfl_xor_sync(0xffffffffu, tm1, 1));
        tm1 = fmaxf(tm1, __shfl_xor_sync(0xffffffffu, tm1, 2));
        float mn0 = fmaxf(m_0, tm0), mn1 = fmaxf(m_1, tm1);
        float al0 = __expf(m_0 - mn0), al1 = __expf(m_1 - mn1);
        m_0 = mn0; m_1 = mn1;

        float rs0 = 0.f, rs1 = 0.f;
#pragma unroll
        for (int ni = 0; ni < 8; ni++) {
            s[ni][0] = __expf(s[ni][0] - mn0);
            s[ni][1] = __expf(s[ni][1] - mn0);
            s[ni][2] = __expf(s[ni][2] - mn1);
            s[ni][3] = __expf(s[ni][3] - mn1);
            rs0 += s[ni][0] + s[ni][1];
            rs1 += s[ni][2] + s[ni][3];
        }
        rs0 += __shfl_xor_sync(0xffffffffu, rs0, 1);
        rs0 += __shfl_xor_sync(0xffffffffu, rs0, 2);
        rs1 += __shfl_xor_sync(0xffffffffu, rs1, 1);
        rs1 += __shfl_xor_sync(0xffffffffu, rs1, 2);
        l_0 = l_0 * al0 + rs0;
        l_1 = l_1 * al1 + rs1;

        unsigned pf[4][4];
#pragma unroll
        for (int j = 0; j < 4; j++) {
            pf[j][0] = packbf(s[2 * j][0],     s[2 * j][1]);
            pf[j][1] = packbf(s[2 * j][2],     s[2 * j][3]);
            pf[j][2] = packbf(s[2 * j + 1][0], s[2 * j + 1][1]);
            pf[j][3] = packbf(s[2 * j + 1][2], s[2 * j + 1][3]);
        }

#pragma unroll
        for (int e = 0; e < 16; e++) {
            o[e][0] *= al0; o[e][1] *= al0;
            o[e][2] *= al1; o[e][3] *= al1;
        }

#pragma unroll
        for (int j = 0; j < 4; j++) {
#pragma unroll
            for (int ej = 0; ej < 8; ej++) {
                unsigned r0, r1, r2, r3;
                ldsm4(r0, r1, r2, r3, va0 + (ej * 16 * QSTR + j * 16) * 2);
                unsigned b0[2] = {r0, r1}, b1[2] = {r2, r3};
                mma_bf16(o[2 * ej],     pf[j], b0);
                mma_bf16(o[2 * ej + 1], pf[j], b1);
            }
        }
    }

    // ---- epilogue: transpose fragments -> smem [e][t], fuse u-gating ----
    __syncthreads();   // all PV reads of vs done before overwriting smbuf
#pragma unroll
    for (int et = 0; et < 16; et++) {
        int ec = et * 8 + 2 * th4;
        os[ec * OSTR + wq + g]           = o[et][0];
        os[(ec + 1) * OSTR + wq + g]     = o[et][1];
        os[ec * OSTR + wq + g + 8]       = o[et][2];
        os[(ec + 1) * OSTR + wq + g + 8] = o[et][3];
    }
    if (th4 == 0) {
        linv[wq + g]     = 1.f / l_0;
        linv[wq + g + 8] = 1.f / l_1;
    }
    __syncthreads();

    const float* ubase = g_uv + (size_t)(b * 2 * E_ + h * EV_) * T_ + qt * 64;
    __nv_bfloat16* wbase = g_w + (size_t)(b * E_ + h * EV_) * T_ + qt * 64;
#pragma unroll
    for (int p = 0; p < 8; p++) {
        int idx = tid + 128 * p;
        int e  = idx >> 3;
        int t8 = (idx & 7) << 3;
        float4 u0 = *(const float4*)(ubase + (size_t)e * T_ + t8);
        float4 u1 = *(const float4*)(ubase + (size_t)e * T_ + t8 + 4);
        const float* orow = os + e * OSTR + t8;
        float w0 = u0.x * orow[0] * linv[t8 + 0];
        float w1 = u0.y * orow[1] * linv[t8 + 1];
        float w2 = u0.z * orow[2] * linv[t8 + 2];
        float w3 = u0.w * orow[3] * linv[t8 + 3];
        float w4 = u1.x * orow[4] * linv[t8 + 4];
        float w5 = u1.y * orow[5] * linv[t8 + 5];
        float w6 = u1.z * orow[6] * linv[t8 + 6];
        float w7 = u1.w * orow[7] * linv[t8 + 7];
        uint4 wv = {packbf(w0, w1), packbf(w2, w3), packbf(w4, w5), packbf(w6, w7)};
        *(uint4*)(wbase + (size_t)e * T_ + t8) = wv;
    }
}

// =============================================================================
// GEMM3: y = x + b_out + W_out @ w   M=512 K=1024 N=1024  (w is bf16, coalesced)
// =============================================================================
__global__ __launch_bounds__(256) void gemm_out_bf16(
    const float* __restrict__ W, const float* __restrict__ x,
    const float* __restrict__ bias)
{
    GEMM_DECL();
    const __nv_bfloat16* wb = g_w + (size_t)b * E_ * T_;
    float4 ar[4];
    uint4  wr[2];

#define LDG_B3(k0)                                                             \
    _Pragma("unroll") for (int p = 0; p < 2; p++) {                            \
        int idx = tid + 256 * p;                                               \
        wr[p] = *(const uint4*)(wb + (size_t)((k0) + (idx >> 4)) * T_ + n0 + (idx & 15) * 8); \
    }

    GEMM_LDG_A(W, E_, 0);
    LDG_B3(0);
    for (int k0 = 0; k0 < E_; k0 += 32) {
#pragma unroll
        for (int p = 0; p < 4; p++) {
            int idx = tid + 256 * p;
            uint2 wa = {packbf(ar[p].x, ar[p].y), packbf(ar[p].z, ar[p].w)};
            *(uint2*)&As[(idx >> 3) * ASTR + (idx & 7) * 4] = wa;
        }
#pragma unroll
        for (int p = 0; p < 2; p++) {
            int idx = tid + 256 * p;
            *(uint4*)&Bs[(idx >> 4) * BSTR + (idx & 15) * 8] = wr[p];
        }
        __syncthreads();
        if (k0 + 32 < E_) {
            GEMM_LDG_A(W, E_, k0 + 32);
            LDG_B3(k0 + 32);
        }
        GEMM_COMPUTE();
        __syncthreads();
    }
    const float* xb = x + (size_t)b * C_ * T_;
    float* yp = g_y + (size_t)b * C_ * T_;
#pragma unroll
    for (int mi = 0; mi < 4; mi++) {
        int m = m0 + wm + mi * 16 + g;
        float bo0 = bias[m], bo1 = bias[m + 8];
#pragma unroll
        for (int ni = 0; ni < 4; ni++) {
            int n = n0 + wn + ni * 8 + 2 * th4;
            float2 x0 = *(const float2*)(xb + (size_t)m * T_ + n);
            float2 x1 = *(const float2*)(xb + (size_t)(m + 8) * T_ + n);
            float2 y0 = {acc[mi][ni][0] + bo0 + x0.x, acc[mi][ni][1] + bo0 + x0.y};
            float2 y1 = {acc[mi][ni][2] + bo1 + x1.x, acc[mi][ni][3] + bo1 + x1.y};
            *(float2*)(yp + (size_t)m * T_ + n)       = y0;
            *(float2*)(yp + (size_t)(m + 8) * T_ + n) = y1;
        }
    }
}

// =============================================================================
// RMSNorm over C
// =============================================================================
__global__ __launch_bounds__(256) void rms2_kernel(
    const float* __restrict__ gamma, float* __restrict__ out)
{
    __shared__ float red[8][32];
    __shared__ float rbuf[32];
    const int b = blockIdx.y;
    const int tseg = threadIdx.x & 31, cseg = threadIdx.x >> 5;
    const int t = blockIdx.x * 32 + tseg;
    const float* yb = g_y + (size_t)b * C_ * T_ + t;
    float ss = 0.f;
#pragma unroll 8
    for (int c = cseg * 64; c < cseg * 64 + 64; c++) {
        float v = yb[(size_t)c * T_];
        ss += v * v;
    }
    red[cseg][tseg] = ss;
    __syncthreads();
    if (cseg == 0) {
        float tot = 0.f;
#pragma unroll
        for (int i = 0; i < 8; i++) tot += red[i][tseg];
        rbuf[tseg] = rsqrtf(tot * (1.f / C_) + 1e-5f);
    }
    __syncthreads();
    float r = rbuf[tseg];
    float* op = out + (size_t)b * C_ * T_ + t;
#pragma unroll 8
    for (int c = cseg * 64; c < cseg * 64 + 64; c++) {
        op[(size_t)c * T_] = yb[(size_t)c * T_] * r * gamma[c];
    }
}

// =============================================================================
// launch
// =============================================================================
extern "C" void kernel_launch(void* const* d_in, const int* in_sizes, int n_in,
                              void* d_out, int out_size)
{
    const float* x      = (const float*)d_in[0];
    const float* W_in   = (const float*)d_in[1];
    const float* b_in   = (const float*)d_in[2];
    const float* W_attn = (const float*)d_in[3];
    const float* b_attn = (const float*)d_in[4];
    const float* w_q    = (const float*)d_in[5];
    const float* b_q    = (const float*)d_in[6];
    const float* w_k    = (const float*)d_in[7];
    const float* b_k    = (const float*)d_in[8];
    const float* W_out  = (const float*)d_in[9];
    const float* b_out  = (const float*)d_in[10];
    const float* gamma  = (const float*)d_in[11];
    float* out = (float*)d_out;

    gemm_uv_bf16<<<dim3(T_ / 128, 2 * E_ / 128, B_), 256>>>(W_in, x, b_in);
    gemm_qk_bf16<<<dim3(T_ / 128, QK_ / 128, B_), 256>>>(W_attn, x, b_attn,
                                                         w_q, b_q, w_k, b_k);
    attn_bf16_kernel<<<dim3(T_ / 64, H_, B_), 128>>>();
    gemm_out_bf16<<<dim3(T_ / 128, C_ / 128, B_), 256>>>(W_out, x, b_out);
    rms2_kernel<<<dim3(T_ / 32, B_), 256>>>(gamma, out);
}

// round 5
// speedup vs baseline: 5.4005x; 1.0177x over previous
#include <cuda_runtime.h>
#include <cuda_bf16.h>
#include <math.h>

#define B_  8
#define C_  512
#define T_  1024
#define E_  1024
#define H_  8
#define HD_ 64
#define QK_ 512
#define EV_ 128

#define SCALE_ 0.13888888888888889f  // log(1024)/log(512)/sqrt(64)

// ---------------- scratch (bf16 intermediates) ----------------
static __device__ __nv_bfloat16 g_u[(size_t)B_ * E_ * T_];    // silu u, [b,e,t]
static __device__ __nv_bfloat16 g_v[(size_t)B_ * E_ * T_];    // silu v, [b,e,t]
static __device__ __nv_bfloat16 g_q[(size_t)B_ * QK_ * T_];   // q*SCALE, [b,d,t]
static __device__ __nv_bfloat16 g_k[(size_t)B_ * QK_ * T_];   // k, [b,d,t]
static __device__ __nv_bfloat16 g_w[(size_t)B_ * E_ * T_];    // u*o/l, [b,e,t]
static __device__ float g_y[(size_t)B_ * C_ * T_];

// ---------------- helpers ----------------
__device__ __forceinline__ unsigned packbf(float lo, float hi) {
    unsigned r;
    asm("cvt.rn.bf16x2.f32 %0, %1, %2;" : "=r"(r) : "f"(hi), "f"(lo));
    return r;
}
__device__ __forceinline__ void mma_bf16(float* d, const unsigned* a, const unsigned* b) {
    asm volatile(
        "mma.sync.aligned.m16n8k16.row.col.f32.bf16.bf16.f32 "
        "{%0,%1,%2,%3}, {%4,%5,%6,%7}, {%8,%9}, {%0,%1,%2,%3};"
        : "+f"(d[0]), "+f"(d[1]), "+f"(d[2]), "+f"(d[3])
        : "r"(a[0]), "r"(a[1]), "r"(a[2]), "r"(a[3]), "r"(b[0]), "r"(b[1]));
}
__device__ __forceinline__ void ldsm4(unsigned& r0, unsigned& r1, unsigned& r2, unsigned& r3,
                                      unsigned addr) {
    asm volatile("ldmatrix.sync.aligned.m8n8.x4.shared.b16 {%0,%1,%2,%3}, [%4];"
                 : "=r"(r0), "=r"(r1), "=r"(r2), "=r"(r3) : "r"(addr));
}
__device__ __forceinline__ void ldsm4t(unsigned& r0, unsigned& r1, unsigned& r2, unsigned& r3,
                                       unsigned addr) {
    asm volatile("ldmatrix.sync.aligned.m8n8.x4.trans.shared.b16 {%0,%1,%2,%3}, [%4];"
                 : "=r"(r0), "=r"(r1), "=r"(r2), "=r"(r3) : "r"(addr));
}

// ---------------- GEMM tiling: 128x128 CTA, BK=32, 8 warps (2x4) ----------------
#define ASTR 40
#define BSTR 136

#define GEMM_DECL()                                                            \
    __shared__ __align__(16) unsigned short As[128 * ASTR];                    \
    __shared__ __align__(16) unsigned short Bs[32 * BSTR];                     \
    const int b   = blockIdx.z;                                                \
    const int m0  = blockIdx.y * 128;                                          \
    const int n0  = blockIdx.x * 128;                                          \
    const int tid = threadIdx.x;                                               \
    const int lane = tid & 31, warp = tid >> 5;                                \
    const int g = lane >> 2, th4 = lane & 3;                                   \
    const int wm = (warp & 1) * 64, wn = (warp >> 1) * 32;                     \
    const unsigned as_b = (unsigned)__cvta_generic_to_shared(As);              \
    const unsigned bs_b = (unsigned)__cvta_generic_to_shared(Bs);              \
    const unsigned a_addr0 = as_b + ((wm + (lane & 15)) * ASTR + (lane >> 4) * 8) * 2; \
    const unsigned b_addr0 = bs_b + ((lane & 15) * BSTR + wn + (lane >> 4) * 8) * 2;   \
    float acc[4][4][4];                                                        \
    _Pragma("unroll") for (int i = 0; i < 4; i++)                              \
    _Pragma("unroll") for (int j = 0; j < 4; j++)                              \
    _Pragma("unroll") for (int r = 0; r < 4; r++) acc[i][j][r] = 0.f;

#define GEMM_LDG_A(W, ldk, k0)                                                 \
    _Pragma("unroll") for (int p = 0; p < 4; p++) {                            \
        int idx = tid + 256 * p;                                               \
        ar[p] = *(const float4*)((W) + (size_t)(m0 + (idx >> 3)) * (ldk) + (k0) + (idx & 7) * 4); \
    }

#define GEMM_STS()                                                             \
    _Pragma("unroll") for (int p = 0; p < 4; p++) {                            \
        int idx = tid + 256 * p;                                               \
        uint2 wa = {packbf(ar[p].x, ar[p].y), packbf(ar[p].z, ar[p].w)};       \
        *(uint2*)&As[(idx >> 3) * ASTR + (idx & 7) * 4] = wa;                  \
        uint2 wb = {packbf(br[p].x, br[p].y), packbf(br[p].z, br[p].w)};       \
        *(uint2*)&Bs[(idx >> 5) * BSTR + (idx & 31) * 4] = wb;                 \
    }

#define GEMM_COMPUTE()                                                         \
    _Pragma("unroll") for (int ks16 = 0; ks16 < 2; ks16++) {                   \
        unsigned af[4][4], bf[4][2];                                           \
        _Pragma("unroll") for (int mi = 0; mi < 4; mi++)                       \
            ldsm4(af[mi][0], af[mi][1], af[mi][2], af[mi][3],                  \
                  a_addr0 + (mi * 16 * ASTR + ks16 * 16) * 2);                 \
        _Pragma("unroll") for (int nj = 0; nj < 2; nj++)                       \
            ldsm4t(bf[nj*2][0], bf[nj*2][1], bf[nj*2+1][0], bf[nj*2+1][1],     \
                   b_addr0 + (ks16 * 16 * BSTR + nj * 16) * 2);                \
        _Pragma("unroll") for (int mi = 0; mi < 4; mi++)                       \
        _Pragma("unroll") for (int ni = 0; ni < 4; ni++)                       \
            mma_bf16(acc[mi][ni], af[mi], bf[ni]);                             \
    }

// =============================================================================
// GEMM1: u,v = silu(W_in @ x + b_in) -> bf16   M=2048 K=512 N=1024
// =============================================================================
__global__ __launch_bounds__(256) void gemm_uv_bf16(
    const float* __restrict__ W, const float* __restrict__ x,
    const float* __restrict__ bias)
{
    GEMM_DECL();
    const float* xb = x + (size_t)b * C_ * T_;
    float4 ar[4], br[4];
    GEMM_LDG_A(W, C_, 0);
#pragma unroll
    for (int p = 0; p < 4; p++) {
        int idx = tid + 256 * p;
        br[p] = *(const float4*)(xb + (size_t)(idx >> 5) * T_ + n0 + (idx & 31) * 4);
    }
    for (int k0 = 0; k0 < C_; k0 += 32) {
        GEMM_STS();
        __syncthreads();
        if (k0 + 32 < C_) {
            GEMM_LDG_A(W, C_, k0 + 32);
#pragma unroll
            for (int p = 0; p < 4; p++) {
                int idx = tid + 256 * p;
                br[p] = *(const float4*)(xb + (size_t)(k0 + 32 + (idx >> 5)) * T_ + n0 + (idx & 31) * 4);
            }
        }
        GEMM_COMPUTE();
        __syncthreads();
    }
    // whole 128-row block is entirely u (m0<E_) or entirely v
    __nv_bfloat16* outp = (m0 < E_)
        ? g_u + (size_t)b * E_ * T_
        : g_v + (size_t)b * E_ * T_ - (size_t)E_ * T_;
#pragma unroll
    for (int mi = 0; mi < 4; mi++) {
        int m = m0 + wm + mi * 16 + g;
        float b0 = bias[m], b1 = bias[m + 8];
#pragma unroll
        for (int ni = 0; ni < 4; ni++) {
            int n = n0 + wn + ni * 8 + 2 * th4;
            float t0 = acc[mi][ni][0] + b0, t1 = acc[mi][ni][1] + b0;
            float t2 = acc[mi][ni][2] + b1, t3 = acc[mi][ni][3] + b1;
            unsigned w0 = packbf(t0 / (1.f + __expf(-t0)), t1 / (1.f + __expf(-t1)));
            unsigned w1 = packbf(t2 / (1.f + __expf(-t2)), t3 / (1.f + __expf(-t3)));
            *(unsigned*)(outp + (size_t)m * T_ + n)       = w0;
            *(unsigned*)(outp + (size_t)(m + 8) * T_ + n) = w1;
        }
    }
}

// =============================================================================
// GEMM2: z = W_attn @ x + b_attn; q=(z*wq+bq)*SCALE, k=z*wk+bk -> bf16
// =============================================================================
__global__ __launch_bounds__(256) void gemm_qk_bf16(
    const float* __restrict__ W, const float* __restrict__ x,
    const float* __restrict__ bias,
    const float* __restrict__ wq, const float* __restrict__ bq,
    const float* __restrict__ wk, const float* __restrict__ bk)
{
    GEMM_DECL();
    const float* xb = x + (size_t)b * C_ * T_;
    float4 ar[4], br[4];
    GEMM_LDG_A(W, C_, 0);
#pragma unroll
    for (int p = 0; p < 4; p++) {
        int idx = tid + 256 * p;
        br[p] = *(const float4*)(xb + (size_t)(idx >> 5) * T_ + n0 + (idx & 31) * 4);
    }
    for (int k0 = 0; k0 < C_; k0 += 32) {
        GEMM_STS();
        __syncthreads();
        if (k0 + 32 < C_) {
            GEMM_LDG_A(W, C_, k0 + 32);
#pragma unroll
            for (int p = 0; p < 4; p++) {
                int idx = tid + 256 * p;
                br[p] = *(const float4*)(xb + (size_t)(k0 + 32 + (idx >> 5)) * T_ + n0 + (idx & 31) * 4);
            }
        }
        GEMM_COMPUTE();
        __syncthreads();
    }
    __nv_bfloat16* qp = g_q + (size_t)b * QK_ * T_;
    __nv_bfloat16* kp = g_k + (size_t)b * QK_ * T_;
#pragma unroll
    for (int mi = 0; mi < 4; mi++) {
        int m = m0 + wm + mi * 16 + g;
        float bi0 = bias[m], bi1 = bias[m + 8];
        float wq0 = wq[m] * SCALE_, bq0 = bq[m] * SCALE_;
        float wk0 = wk[m], bk0 = bk[m];
        float wq1 = wq[m + 8] * SCALE_, bq1 = bq[m + 8] * SCALE_;
        float wk1 = wk[m + 8], bk1 = bk[m + 8];
#pragma unroll
        for (int ni = 0; ni < 4; ni++) {
            int n = n0 + wn + ni * 8 + 2 * th4;
            float z0 = acc[mi][ni][0] + bi0, z1 = acc[mi][ni][1] + bi0;
            float z2 = acc[mi][ni][2] + bi1, z3 = acc[mi][ni][3] + bi1;
            *(unsigned*)(qp + (size_t)m * T_ + n)       = packbf(z0 * wq0 + bq0, z1 * wq0 + bq0);
            *(unsigned*)(qp + (size_t)(m + 8) * T_ + n) = packbf(z2 * wq1 + bq1, z3 * wq1 + bq1);
            *(unsigned*)(kp + (size_t)m * T_ + n)       = packbf(z0 * wk0 + bk0, z1 * wk0 + bk0);
            *(unsigned*)(kp + (size_t)(m + 8) * T_ + n) = packbf(z2 * wk1 + bk1, z3 * wk1 + bk1);
        }
    }
}

// =============================================================================
// Flash attention bf16, BQ=128 (8 warps x 16 rows), BKV=64.
// Inputs already bf16: fills are pure copies. Fused u-gating epilogue.
// =============================================================================
#define QS2 136   // qs stride (q-dim 128 cols + 8 pad)
#define KS2 72    // ks/vs stride

__global__ __launch_bounds__(256) void attn_bf16_kernel()
{
    __shared__ __align__(16) char smbuf[(64 * QS2 + 64 * KS2 + 128 * KS2) * 2];
    __shared__ float linv[128];
    unsigned short* qs = (unsigned short*)smbuf;          // [d][q] 64x136
    unsigned short* ks = qs + 64 * QS2;                   // [d][kv] 64x72
    unsigned short* vs = ks + 64 * KS2;                   // [e][kv] 128x72
    float* os = (float*)smbuf;                            // [64 e][136 t] fp32 (epilogue)

    const int b  = blockIdx.z;
    const int h  = blockIdx.y;
    const int qt = blockIdx.x;
    const int tid = threadIdx.x;
    const int lane = tid & 31, warp = tid >> 5;
    const int g = lane >> 2, th4 = lane & 3;
    const int wq = warp * 16;

    const __nv_bfloat16* qbase = g_q + (size_t)(b * QK_ + h * HD_) * T_;
    const __nv_bfloat16* kbase = g_k + (size_t)(b * QK_ + h * HD_) * T_;
    const __nv_bfloat16* vbase = g_v + (size_t)(b * E_ + h * EV_) * T_;

    const unsigned qs_b = (unsigned)__cvta_generic_to_shared(qs);
    const unsigned ks_b = (unsigned)__cvta_generic_to_shared(ks);
    const unsigned vs_b = (unsigned)__cvta_generic_to_shared(vs);

    const unsigned qa0 = qs_b + ((((lane >> 4) << 3) + (lane & 7)) * QS2 + wq + (lane & 8)) * 2;
    const unsigned ka0 = ks_b + (((lane & 7) + ((lane >> 3) & 1) * 8) * KS2 + ((lane >> 4) & 1) * 8) * 2;
    const unsigned va0 = vs_b + (((lane & 7) + ((lane >> 4) & 1) * 8) * KS2 + (lane & 8)) * 2;

    // load Q tile [64 d][128 q]: 1024 uint4
#pragma unroll
    for (int p = 0; p < 4; p++) {
        int idx = tid + 256 * p;
        int d  = idx >> 4;
        int q8 = (idx & 15) << 3;
        *(uint4*)&qs[d * QS2 + q8] =
            *(const uint4*)(qbase + (size_t)d * T_ + qt * 128 + q8);
    }

    float o[16][4];
#pragma unroll
    for (int e = 0; e < 16; e++)
#pragma unroll
        for (int r = 0; r < 4; r++) o[e][r] = 0.f;
    float m_0 = -1e30f, m_1 = -1e30f, l_0 = 0.f, l_1 = 0.f;

    for (int kt = 0; kt < 16; kt++) {
        const int kt0 = kt * 64;
        __syncthreads();
        // K tile [64 d][64 kv]: 512 uint4
#pragma unroll
        for (int p = 0; p < 2; p++) {
            int idx = tid + 256 * p;
            int d  = idx >> 3;
            int c8 = (idx & 7) << 3;
            *(uint4*)&ks[d * KS2 + c8] =
                *(const uint4*)(kbase + (size_t)d * T_ + kt0 + c8);
        }
        // V tile [128 e][64 kv]: 1024 uint4
#pragma unroll
        for (int p = 0; p < 4; p++) {
            int idx = tid + 256 * p;
            int e  = idx >> 3;
            int c8 = (idx & 7) << 3;
            *(uint4*)&vs[e * KS2 + c8] =
                *(const uint4*)(vbase + (size_t)e * T_ + kt0 + c8);
        }
        __syncthreads();

        // S = Q K^T : per warp 16x64
        float s[8][4];
#pragma unroll
        for (int ni = 0; ni < 8; ni++)
#pragma unroll
            for (int r = 0; r < 4; r++) s[ni][r] = 0.f;
#pragma unroll
        for (int kd = 0; kd < 4; kd++) {
            unsigned a[4];
            ldsm4t(a[0], a[1], a[2], a[3], qa0 + kd * 16 * QS2 * 2);
#pragma unroll
            for (int kvj = 0; kvj < 4; kvj++) {
                unsigned r0, r1, r2, r3;
                ldsm4t(r0, r1, r2, r3, ka0 + (kd * 16 * KS2 + kvj * 16) * 2);
                unsigned b0[2] = {r0, r1}, b1[2] = {r2, r3};
                mma_bf16(s[2 * kvj],     a, b0);
                mma_bf16(s[2 * kvj + 1], a, b1);
            }
        }

        // online softmax
        float tm0 = -1e30f, tm1 = -1e30f;
#pragma unroll
        for (int ni = 0; ni < 8; ni++) {
            tm0 = fmaxf(tm0, fmaxf(s[ni][0], s[ni][1]));
            tm1 = fmaxf(tm1, fmaxf(s[ni][2], s[ni][3]));
        }
        tm0 = fmaxf(tm0, __shfl_xor_sync(0xffffffffu, tm0, 1));
        tm0 = fmaxf(tm0, __shfl_xor_sync(0xffffffffu, tm0, 2));
        tm1 = fmaxf(tm1, __shfl_xor_sync(0xffffffffu, tm1, 1));
        tm1 = fmaxf(tm1, __shfl_xor_sync(0xffffffffu, tm1, 2));
        float mn0 = fmaxf(m_0, tm0), mn1 = fmaxf(m_1, tm1);
        float al0 = __expf(m_0 - mn0), al1 = __expf(m_1 - mn1);
        m_0 = mn0; m_1 = mn1;

        float rs0 = 0.f, rs1 = 0.f;
#pragma unroll
        for (int ni = 0; ni < 8; ni++) {
            s[ni][0] = __expf(s[ni][0] - mn0);
            s[ni][1] = __expf(s[ni][1] - mn0);
            s[ni][2] = __expf(s[ni][2] - mn1);
            s[ni][3] = __expf(s[ni][3] - mn1);
            rs0 += s[ni][0] + s[ni][1];
            rs1 += s[ni][2] + s[ni][3];
        }
        rs0 += __shfl_xor_sync(0xffffffffu, rs0, 1);
        rs0 += __shfl_xor_sync(0xffffffffu, rs0, 2);
        rs1 += __shfl_xor_sync(0xffffffffu, rs1, 1);
        rs1 += __shfl_xor_sync(0xffffffffu, rs1, 2);
        l_0 = l_0 * al0 + rs0;
        l_1 = l_1 * al1 + rs1;

        unsigned pf[4][4];
#pragma unroll
        for (int j = 0; j < 4; j++) {
            pf[j][0] = packbf(s[2 * j][0],     s[2 * j][1]);
            pf[j][1] = packbf(s[2 * j][2],     s[2 * j][3]);
            pf[j][2] = packbf(s[2 * j + 1][0], s[2 * j + 1][1]);
            pf[j][3] = packbf(s[2 * j + 1][2], s[2 * j + 1][3]);
        }

#pragma unroll
        for (int e = 0; e < 16; e++) {
            o[e][0] *= al0; o[e][1] *= al0;
            o[e][2] *= al1; o[e][3] *= al1;
        }

#pragma unroll
        for (int j = 0; j < 4; j++) {
#pragma unroll
            for (int ej = 0; ej < 8; ej++) {
                unsigned r0, r1, r2, r3;
                ldsm4(r0, r1, r2, r3, va0 + (ej * 16 * KS2 + j * 16) * 2);
                unsigned b0[2] = {r0, r1}, b1[2] = {r2, r3};
                mma_bf16(o[2 * ej],     pf[j], b0);
                mma_bf16(o[2 * ej + 1], pf[j], b1);
            }
        }
    }

    if (th4 == 0) {
        linv[wq + g]     = 1.f / l_0;
        linv[wq + g + 8] = 1.f / l_1;
    }

    // ---- epilogue in two e-halves: transpose -> smem [e][t], fuse u-gating ----
    const __nv_bfloat16* ubase = g_u + (size_t)(b * E_ + h * EV_) * T_ + qt * 128;
    __nv_bfloat16* wbase = g_w + (size_t)(b * E_ + h * EV_) * T_ + qt * 128;
#pragma unroll
    for (int eh = 0; eh < 2; eh++) {
        __syncthreads();   // half 0: all PV reads of vs done; half 1: gating reads done
#pragma unroll
        for (int et = eh * 8; et < eh * 8 + 8; et++) {
            int ec = et * 8 + 2 * th4 - eh * 64;   // 0..63
            os[ec * QS2 + wq + g]           = o[et][0];
            os[(ec + 1) * QS2 + wq + g]     = o[et][1];
            os[ec * QS2 + wq + g + 8]       = o[et][2];
            os[(ec + 1) * QS2 + wq + g + 8] = o[et][3];
        }
        __syncthreads();
#pragma unroll
        for (int p = 0; p < 4; p++) {
            int idx = tid + 256 * p;
            int e  = idx >> 4;          // 0..63 local
            int t8 = (idx & 15) << 3;
            int eg = eh * 64 + e;
            uint4 uv = *(const uint4*)(ubase + (size_t)eg * T_ + t8);
            const __nv_bfloat162* up = (const __nv_bfloat162*)&uv;
            const float* orow = os + e * QS2 + t8;
            float2 u0 = __bfloat1622float2(up[0]);
            float2 u1 = __bfloat1622float2(up[1]);
            float2 u2 = __bfloat1622float2(up[2]);
            float2 u3 = __bfloat1622float2(up[3]);
            uint4 wv = {
                packbf(u0.x * orow[0] * linv[t8 + 0], u0.y * orow[1] * linv[t8 + 1]),
                packbf(u1.x * orow[2] * linv[t8 + 2], u1.y * orow[3] * linv[t8 + 3]),
                packbf(u2.x * orow[4] * linv[t8 + 4], u2.y * orow[5] * linv[t8 + 5]),
                packbf(u3.x * orow[6] * linv[t8 + 6], u3.y * orow[7] * linv[t8 + 7])};
            *(uint4*)(wbase + (size_t)eg * T_ + t8) = wv;
        }
    }
}

// =============================================================================
// GEMM3: y = x + b_out + W_out @ w   M=512 K=1024 N=1024  (w bf16, coalesced)
// =============================================================================
__global__ __launch_bounds__(256) void gemm_out_bf16(
    const float* __restrict__ W, const float* __restrict__ x,
    const float* __restrict__ bias)
{
    GEMM_DECL();
    const __nv_bfloat16* wb = g_w + (size_t)b * E_ * T_;
    float4 ar[4];
    uint4  wr[2];

#define LDG_B3(k0)                                                             \
    _Pragma("unroll") for (int p = 0; p < 2; p++) {                            \
        int idx = tid + 256 * p;                                               \
        wr[p] = *(const uint4*)(wb + (size_t)((k0) + (idx >> 4)) * T_ + n0 + (idx & 15) * 8); \
    }

    GEMM_LDG_A(W, E_, 0);
    LDG_B3(0);
    for (int k0 = 0; k0 < E_; k0 += 32) {
#pragma unroll
        for (int p = 0; p < 4; p++) {
            int idx = tid + 256 * p;
            uint2 wa = {packbf(ar[p].x, ar[p].y), packbf(ar[p].z, ar[p].w)};
            *(uint2*)&As[(idx >> 3) * ASTR + (idx & 7) * 4] = wa;
        }
#pragma unroll
        for (int p = 0; p < 2; p++) {
            int idx = tid + 256 * p;
            *(uint4*)&Bs[(idx >> 4) * BSTR + (idx & 15) * 8] = wr[p];
        }
        __syncthreads();
        if (k0 + 32 < E_) {
            GEMM_LDG_A(W, E_, k0 + 32);
            LDG_B3(k0 + 32);
        }
        GEMM_COMPUTE();
        __syncthreads();
    }
    const float* xb = x + (size_t)b * C_ * T_;
    float* yp = g_y + (size_t)b * C_ * T_;
#pragma unroll
    for (int mi = 0; mi < 4; mi++) {
        int m = m0 + wm + mi * 16 + g;
        float bo0 = bias[m], bo1 = bias[m + 8];
#pragma unroll
        for (int ni = 0; ni < 4; ni++) {
            int n = n0 + wn + ni * 8 + 2 * th4;
            float2 x0 = *(const float2*)(xb + (size_t)m * T_ + n);
            float2 x1 = *(const float2*)(xb + (size_t)(m + 8) * T_ + n);
            float2 y0 = {acc[mi][ni][0] + bo0 + x0.x, acc[mi][ni][1] + bo0 + x0.y};
            float2 y1 = {acc[mi][ni][2] + bo1 + x1.x, acc[mi][ni][3] + bo1 + x1.y};
            *(float2*)(yp + (size_t)m * T_ + n)       = y0;
            *(float2*)(yp + (size_t)(m + 8) * T_ + n) = y1;
        }
    }
}

// =============================================================================
// RMSNorm over C
// =============================================================================
__global__ __launch_bounds__(256) void rms2_kernel(
    const float* __restrict__ gamma, float* __restrict__ out)
{
    __shared__ float red[8][32];
    __shared__ float rbuf[32];
    const int b = blockIdx.y;
    const int tseg = threadIdx.x & 31, cseg = threadIdx.x >> 5;
    const int t = blockIdx.x * 32 + tseg;
    const float* yb = g_y + (size_t)b * C_ * T_ + t;
    float ss = 0.f;
#pragma unroll 8
    for (int c = cseg * 64; c < cseg * 64 + 64; c++) {
        float v = yb[(size_t)c * T_];
        ss += v * v;
    }
    red[cseg][tseg] = ss;
    __syncthreads();
    if (cseg == 0) {
        float tot = 0.f;
#pragma unroll
        for (int i = 0; i < 8; i++) tot += red[i][tseg];
        rbuf[tseg] = rsqrtf(tot * (1.f / C_) + 1e-5f);
    }
    __syncthreads();
    float r = rbuf[tseg];
    float* op = out + (size_t)b * C_ * T_ + t;
#pragma unroll 8
    for (int c = cseg * 64; c < cseg * 64 + 64; c++) {
        op[(size_t)c * T_] = yb[(size_t)c * T_] * r * gamma[c];
    }
}

// =============================================================================
// launch
// =============================================================================
extern "C" void kernel_launch(void* const* d_in, const int* in_sizes, int n_in,
                              void* d_out, int out_size)
{
    const float* x      = (const float*)d_in[0];
    const float* W_in   = (const float*)d_in[1];
    const float* b_in   = (const float*)d_in[2];
    const float* W_attn = (const float*)d_in[3];
    const float* b_attn = (const float*)d_in[4];
    const float* w_q    = (const float*)d_in[5];
    const float* b_q    = (const float*)d_in[6];
    const float* w_k    = (const float*)d_in[7];
    const float* b_k    = (const float*)d_in[8];
    const float* W_out  = (const float*)d_in[9];
    const float* b_out  = (const float*)d_in[10];
    const float* gamma  = (const float*)d_in[11];
    float* out = (float*)d_out;

    gemm_uv_bf16<<<dim3(T_ / 128, 2 * E_ / 128, B_), 256>>>(W_in, x, b_in);
    gemm_qk_bf16<<<dim3(T_ / 128, QK_ / 128, B_), 256>>>(W_attn, x, b_attn,
                                                         w_q, b_q, w_k, b_k);
    attn_bf16_kernel<<<dim3(T_ / 128, H_, B_), 256>>>();
    gemm_out_bf16<<<dim3(T_ / 128, C_ / 128, B_), 256>>>(W_out, x, b_out);
    rms2_kernel<<<dim3(T_ / 32, B_), 256>>>(gamma, out);
}

// round 6
// speedup vs baseline: 7.3484x; 1.3607x over previous
#include <cuda_runtime.h>
#include <cuda_bf16.h>
#include <math.h>

#define B_  8
#define C_  512
#define T_  1024
#define E_  1024
#define H_  8
#define HD_ 64
#define QK_ 512
#define EV_ 128

// log(1024)/log(512)/sqrt(64) * log2(e)  (exp2-based softmax)
#define QSCALE_ 0.20037157933881626f

// ---------------- scratch (bf16 intermediates) ----------------
static __device__ __nv_bfloat16 g_u[(size_t)B_ * E_ * T_];
static __device__ __nv_bfloat16 g_v[(size_t)B_ * E_ * T_];
static __device__ __nv_bfloat16 g_q[(size_t)B_ * QK_ * T_];   // pre-scaled
static __device__ __nv_bfloat16 g_k[(size_t)B_ * QK_ * T_];
static __device__ __nv_bfloat16 g_w[(size_t)B_ * E_ * T_];
static __device__ float g_y[(size_t)B_ * C_ * T_];
// bf16 copies of fp32 inputs
static __device__ __nv_bfloat16 g_wi[(size_t)2 * E_ * C_];
static __device__ __nv_bfloat16 g_wa[(size_t)QK_ * C_];
static __device__ __nv_bfloat16 g_wo[(size_t)C_ * E_];
static __device__ __nv_bfloat16 g_xb[(size_t)B_ * C_ * T_];

// ---------------- helpers ----------------
__device__ __forceinline__ unsigned packbf(float lo, float hi) {
    unsigned r;
    asm("cvt.rn.bf16x2.f32 %0, %1, %2;" : "=r"(r) : "f"(hi), "f"(lo));
    return r;
}
__device__ __forceinline__ void mma_bf16(float* d, const unsigned* a, const unsigned* b) {
    asm volatile(
        "mma.sync.aligned.m16n8k16.row.col.f32.bf16.bf16.f32 "
        "{%0,%1,%2,%3}, {%4,%5,%6,%7}, {%8,%9}, {%0,%1,%2,%3};"
        : "+f"(d[0]), "+f"(d[1]), "+f"(d[2]), "+f"(d[3])
        : "r"(a[0]), "r"(a[1]), "r"(a[2]), "r"(a[3]), "r"(b[0]), "r"(b[1]));
}
__device__ __forceinline__ void ldsm4(unsigned& r0, unsigned& r1, unsigned& r2, unsigned& r3,
                                      unsigned addr) {
    asm volatile("ldmatrix.sync.aligned.m8n8.x4.shared.b16 {%0,%1,%2,%3}, [%4];"
                 : "=r"(r0), "=r"(r1), "=r"(r2), "=r"(r3) : "r"(addr));
}
__device__ __forceinline__ void ldsm4t(unsigned& r0, unsigned& r1, unsigned& r2, unsigned& r3,
                                       unsigned addr) {
    asm volatile("ldmatrix.sync.aligned.m8n8.x4.trans.shared.b16 {%0,%1,%2,%3}, [%4];"
                 : "=r"(r0), "=r"(r1), "=r"(r2), "=r"(r3) : "r"(addr));
}

// ---------------- fp32 -> bf16 conversion (prep) ----------------
__global__ __launch_bounds__(256) void conv_bf16(
    const float* __restrict__ src, __nv_bfloat16* __restrict__ dst)
{
    size_t i = ((size_t)blockIdx.x * 256 + threadIdx.x) * 8;
    float4 a = *(const float4*)(src + i);
    float4 b = *(const float4*)(src + i + 4);
    uint4 w = {packbf(a.x, a.y), packbf(a.z, a.w), packbf(b.x, b.y), packbf(b.z, b.w)};
    *(uint4*)(dst + i) = w;
}

// ---------------- GEMM tiling: 128x128 CTA, BK=32, 8 warps (2x4) ----------------
#define ASTR 40
#define BSTR 136

#define GEMM_DECL()                                                            \
    __shared__ __align__(16) unsigned short As[128 * ASTR];                    \
    __shared__ __align__(16) unsigned short Bs[32 * BSTR];                     \
    const int b   = blockIdx.z;                                                \
    const int m0  = blockIdx.y * 128;                                          \
    const int n0  = blockIdx.x * 128;                                          \
    const int tid = threadIdx.x;                                               \
    const int lane = tid & 31, warp = tid >> 5;                                \
    const int g = lane >> 2, th4 = lane & 3;                                   \
    const int wm = (warp & 1) * 64, wn = (warp >> 1) * 32;                     \
    const unsigned as_b = (unsigned)__cvta_generic_to_shared(As);              \
    const unsigned bs_b = (unsigned)__cvta_generic_to_shared(Bs);              \
    const unsigned a_addr0 = as_b + ((wm + (lane & 15)) * ASTR + (lane >> 4) * 8) * 2; \
    const unsigned b_addr0 = bs_b + ((lane & 15) * BSTR + wn + (lane >> 4) * 8) * 2;   \
    float acc[4][4][4];                                                        \
    _Pragma("unroll") for (int i = 0; i < 4; i++)                              \
    _Pragma("unroll") for (int j = 0; j < 4; j++)                              \
    _Pragma("unroll") for (int r = 0; r < 4; r++) acc[i][j][r] = 0.f;          \
    uint4 ar[2], br[2];

// A tile: 128 rows x 32 bf16; 512 uint4, 2/thread
#define GEMM_LDG_A(Wb, ldk, k0)                                                \
    _Pragma("unroll") for (int p = 0; p < 2; p++) {                            \
        int idx = tid + 256 * p;                                               \
        ar[p] = *(const uint4*)((Wb) + (size_t)(m0 + (idx >> 2)) * (ldk) + (k0) + (idx & 3) * 8); \
    }
// B tile: 32 rows x 128 bf16; 512 uint4, 2/thread
#define GEMM_LDG_B(Xb, k0)                                                     \
    _Pragma("unroll") for (int p = 0; p < 2; p++) {                            \
        int idx = tid + 256 * p;                                               \
        br[p] = *(const uint4*)((Xb) + (size_t)((k0) + (idx >> 4)) * T_ + n0 + (idx & 15) * 8); \
    }
#define GEMM_STS()                                                             \
    _Pragma("unroll") for (int p = 0; p < 2; p++) {                            \
        int idx = tid + 256 * p;                                               \
        *(uint4*)&As[(idx >> 2) * ASTR + (idx & 3) * 8]   = ar[p];             \
        *(uint4*)&Bs[(idx >> 4) * BSTR + (idx & 15) * 8]  = br[p];             \
    }

#define GEMM_COMPUTE()                                                         \
    _Pragma("unroll") for (int ks16 = 0; ks16 < 2; ks16++) {                   \
        unsigned af[4][4], bf[4][2];                                           \
        _Pragma("unroll") for (int mi = 0; mi < 4; mi++)                       \
            ldsm4(af[mi][0], af[mi][1], af[mi][2], af[mi][3],                  \
                  a_addr0 + (mi * 16 * ASTR + ks16 * 16) * 2);                 \
        _Pragma("unroll") for (int nj = 0; nj < 2; nj++)                       \
            ldsm4t(bf[nj*2][0], bf[nj*2][1], bf[nj*2+1][0], bf[nj*2+1][1],     \
                   b_addr0 + (ks16 * 16 * BSTR + nj * 16) * 2);                \
        _Pragma("unroll") for (int mi = 0; mi < 4; mi++)                       \
        _Pragma("unroll") for (int ni = 0; ni < 4; ni++)                       \
            mma_bf16(acc[mi][ni], af[mi], bf[ni]);                             \
    }

#define GEMM_MAINLOOP(Wb, ldk, KK, Xb)                                         \
    GEMM_LDG_A(Wb, ldk, 0);                                                    \
    GEMM_LDG_B(Xb, 0);                                                         \
    for (int k0 = 0; k0 < (KK); k0 += 32) {                                    \
        GEMM_STS();                                                            \
        __syncthreads();                                                       \
        if (k0 + 32 < (KK)) {                                                  \
            GEMM_LDG_A(Wb, ldk, k0 + 32);                                      \
            GEMM_LDG_B(Xb, k0 + 32);                                           \
        }                                                                      \
        GEMM_COMPUTE();                                                        \
        __syncthreads();                                                       \
    }

// =============================================================================
// GEMM1: u,v = silu(W_in @ x + b_in) -> bf16   M=2048 K=512 N=1024
// =============================================================================
__global__ __launch_bounds__(256) void gemm_uv_bf16(const float* __restrict__ bias)
{
    GEMM_DECL();
    const __nv_bfloat16* xb = g_xb + (size_t)b * C_ * T_;
    GEMM_MAINLOOP(g_wi, C_, C_, xb);
    __nv_bfloat16* outp = (m0 < E_)
        ? g_u + (size_t)b * E_ * T_
        : g_v + (size_t)b * E_ * T_ - (size_t)E_ * T_;
#pragma unroll
    for (int mi = 0; mi < 4; mi++) {
        int m = m0 + wm + mi * 16 + g;
        float b0 = bias[m], b1 = bias[m + 8];
#pragma unroll
        for (int ni = 0; ni < 4; ni++) {
            int n = n0 + wn + ni * 8 + 2 * th4;
            float t0 = acc[mi][ni][0] + b0, t1 = acc[mi][ni][1] + b0;
            float t2 = acc[mi][ni][2] + b1, t3 = acc[mi][ni][3] + b1;
            unsigned w0 = packbf(t0 / (1.f + __expf(-t0)), t1 / (1.f + __expf(-t1)));
            unsigned w1 = packbf(t2 / (1.f + __expf(-t2)), t3 / (1.f + __expf(-t3)));
            *(unsigned*)(outp + (size_t)m * T_ + n)       = w0;
            *(unsigned*)(outp + (size_t)(m + 8) * T_ + n) = w1;
        }
    }
}

// =============================================================================
// GEMM2: z = W_attn @ x + b_attn; q=(z*wq+bq)*QSCALE, k=z*wk+bk -> bf16
// =============================================================================
__global__ __launch_bounds__(256) void gemm_qk_bf16(
    const float* __restrict__ bias,
    const float* __restrict__ wq, const float* __restrict__ bq,
    const float* __restrict__ wk, const float* __restrict__ bk)
{
    GEMM_DECL();
    const __nv_bfloat16* xb = g_xb + (size_t)b * C_ * T_;
    GEMM_MAINLOOP(g_wa, C_, C_, xb);
    __nv_bfloat16* qp = g_q + (size_t)b * QK_ * T_;
    __nv_bfloat16* kp = g_k + (size_t)b * QK_ * T_;
#pragma unroll
    for (int mi = 0; mi < 4; mi++) {
        int m = m0 + wm + mi * 16 + g;
        float bi0 = bias[m], bi1 = bias[m + 8];
        float wq0 = wq[m] * QSCALE_, bq0 = bq[m] * QSCALE_;
        float wk0 = wk[m], bk0 = bk[m];
        float wq1 = wq[m + 8] * QSCALE_, bq1 = bq[m + 8] * QSCALE_;
        float wk1 = wk[m + 8], bk1 = bk[m + 8];
#pragma unroll
        for (int ni = 0; ni < 4; ni++) {
            int n = n0 + wn + ni * 8 + 2 * th4;
            float z0 = acc[mi][ni][0] + bi0, z1 = acc[mi][ni][1] + bi0;
            float z2 = acc[mi][ni][2] + bi1, z3 = acc[mi][ni][3] + bi1;
            *(unsigned*)(qp + (size_t)m * T_ + n)       = packbf(z0 * wq0 + bq0, z1 * wq0 + bq0);
            *(unsigned*)(qp + (size_t)(m + 8) * T_ + n) = packbf(z2 * wq1 + bq1, z3 * wq1 + bq1);
            *(unsigned*)(kp + (size_t)m * T_ + n)       = packbf(z0 * wk0 + bk0, z1 * wk0 + bk0);
            *(unsigned*)(kp + (size_t)(m + 8) * T_ + n) = packbf(z2 * wk1 + bk1, z3 * wk1 + bk1);
        }
    }
}

// =============================================================================
// Flash attention bf16, BQ=128 (8 warps x 16 rows), BKV=64.
// No-max softmax: scores here are bounded (|s_scaled| << 80), so
// softmax(s) = exp2(s') / sum exp2(s') needs no running max: no rescaling,
// no per-tile reductions. l accumulated per-thread, reduced once at end.
// =============================================================================
#define QS2 136
#define KS2 72

__global__ __launch_bounds__(256) void attn_bf16_kernel()
{
    __shared__ __align__(16) char smbuf[(64 * QS2 + 64 * KS2 + 128 * KS2) * 2];
    unsigned short* qs = (unsigned short*)smbuf;          // [d][q] 64x136
    unsigned short* ks = qs + 64 * QS2;                   // [d][kv] 64x72
    unsigned short* vs = ks + 64 * KS2;                   // [e][kv] 128x72
    float* os = (float*)smbuf;                            // [64 e][136 t] (epilogue)

    const int b  = blockIdx.z;
    const int h  = blockIdx.y;
    const int qt = blockIdx.x;
    const int tid = threadIdx.x;
    const int lane = tid & 31, warp = tid >> 5;
    const int g = lane >> 2, th4 = lane & 3;
    const int wq = warp * 16;

    const __nv_bfloat16* qbase = g_q + (size_t)(b * QK_ + h * HD_) * T_;
    const __nv_bfloat16* kbase = g_k + (size_t)(b * QK_ + h * HD_) * T_;
    const __nv_bfloat16* vbase = g_v + (size_t)(b * E_ + h * EV_) * T_;

    const unsigned qs_b = (unsigned)__cvta_generic_to_shared(qs);
    const unsigned ks_b = (unsigned)__cvta_generic_to_shared(ks);
    const unsigned vs_b = (unsigned)__cvta_generic_to_shared(vs);

    const unsigned qa0 = qs_b + ((((lane >> 4) << 3) + (lane & 7)) * QS2 + wq + (lane & 8)) * 2;
    const unsigned ka0 = ks_b + (((lane & 7) + ((lane >> 3) & 1) * 8) * KS2 + ((lane >> 4) & 1) * 8) * 2;
    const unsigned va0 = vs_b + (((lane & 7) + ((lane >> 4) & 1) * 8) * KS2 + (lane & 8)) * 2;

#pragma unroll
    for (int p = 0; p < 4; p++) {
        int idx = tid + 256 * p;
        int d  = idx >> 4;
        int q8 = (idx & 15) << 3;
        *(uint4*)&qs[d * QS2 + q8] =
            *(const uint4*)(qbase + (size_t)d * T_ + qt * 128 + q8);
    }

    float o[16][4];
#pragma unroll
    for (int e = 0; e < 16; e++)
#pragma unroll
        for (int r = 0; r < 4; r++) o[e][r] = 0.f;
    float l_0 = 0.f, l_1 = 0.f;

    for (int kt = 0; kt < 16; kt++) {
        const int kt0 = kt * 64;
        __syncthreads();
#pragma unroll
        for (int p = 0; p < 2; p++) {
            int idx = tid + 256 * p;
            int d  = idx >> 3;
            int c8 = (idx & 7) << 3;
            *(uint4*)&ks[d * KS2 + c8] =
                *(const uint4*)(kbase + (size_t)d * T_ + kt0 + c8);
        }
#pragma unroll
        for (int p = 0; p < 4; p++) {
            int idx = tid + 256 * p;
            int e  = idx >> 3;
            int c8 = (idx & 7) << 3;
            *(uint4*)&vs[e * KS2 + c8] =
                *(const uint4*)(vbase + (size_t)e * T_ + kt0 + c8);
        }
        __syncthreads();

        // S = Q K^T (q pre-scaled by QSCALE*log2e)
        float s[8][4];
#pragma unroll
        for (int ni = 0; ni < 8; ni++)
#pragma unroll
            for (int r = 0; r < 4; r++) s[ni][r] = 0.f;
#pragma unroll
        for (int kd = 0; kd < 4; kd++) {
            unsigned a[4];
            ldsm4t(a[0], a[1], a[2], a[3], qa0 + kd * 16 * QS2 * 2);
#pragma unroll
            for (int kvj = 0; kvj < 4; kvj++) {
                unsigned r0, r1, r2, r3;
                ldsm4t(r0, r1, r2, r3, ka0 + (kd * 16 * KS2 + kvj * 16) * 2);
                unsigned b0[2] = {r0, r1}, b1[2] = {r2, r3};
                mma_bf16(s[2 * kvj],     a, b0);
                mma_bf16(s[2 * kvj + 1], a, b1);
            }
        }

        // P = exp2(S); accumulate row sums per-thread
        unsigned pf[4][4];
#pragma unroll
        for (int j = 0; j < 4; j++) {
            float p00 = exp2f(s[2 * j][0]),     p01 = exp2f(s[2 * j][1]);
            float p02 = exp2f(s[2 * j][2]),     p03 = exp2f(s[2 * j][3]);
            float p10 = exp2f(s[2 * j + 1][0]), p11 = exp2f(s[2 * j + 1][1]);
            float p12 = exp2f(s[2 * j + 1][2]), p13 = exp2f(s[2 * j + 1][3]);
            l_0 += p00 + p01 + p10 + p11;
            l_1 += p02 + p03 + p12 + p13;
            pf[j][0] = packbf(p00, p01);
            pf[j][1] = packbf(p02, p03);
            pf[j][2] = packbf(p10, p11);
            pf[j][3] = packbf(p12, p13);
        }

        // O += P V
#pragma unroll
        for (int j = 0; j < 4; j++) {
#pragma unroll
            for (int ej = 0; ej < 8; ej++) {
                unsigned r0, r1, r2, r3;
                ldsm4(r0, r1, r2, r3, va0 + (ej * 16 * KS2 + j * 16) * 2);
                unsigned b0[2] = {r0, r1}, b1[2] = {r2, r3};
                mma_bf16(o[2 * ej],     pf[j], b0);
                mma_bf16(o[2 * ej + 1], pf[j], b1);
            }
        }
    }

    // final row-sum reduce + normalize in registers
    l_0 += __shfl_xor_sync(0xffffffffu, l_0, 1);
    l_0 += __shfl_xor_sync(0xffffffffu, l_0, 2);
    l_1 += __shfl_xor_sync(0xffffffffu, l_1, 1);
    l_1 += __shfl_xor_sync(0xffffffffu, l_1, 2);
    float inv0 = 1.f / l_0, inv1 = 1.f / l_1;
#pragma unroll
    for (int e = 0; e < 16; e++) {
        o[e][0] *= inv0; o[e][1] *= inv0;
        o[e][2] *= inv1; o[e][3] *= inv1;
    }

    // ---- epilogue in two e-halves: transpose -> smem [e][t], fuse u-gating ----
    const __nv_bfloat16* ubase = g_u + (size_t)(b * E_ + h * EV_) * T_ + qt * 128;
    __nv_bfloat16* wbase = g_w + (size_t)(b * E_ + h * EV_) * T_ + qt * 128;
#pragma unroll
    for (int eh = 0; eh < 2; eh++) {
        __syncthreads();
#pragma unroll
        for (int et = eh * 8; et < eh * 8 + 8; et++) {
            int ec = et * 8 + 2 * th4 - eh * 64;
            os[ec * QS2 + wq + g]           = o[et][0];
            os[(ec + 1) * QS2 + wq + g]     = o[et][1];
            os[ec * QS2 + wq + g + 8]       = o[et][2];
            os[(ec + 1) * QS2 + wq + g + 8] = o[et][3];
        }
        __syncthreads();
#pragma unroll
        for (int p = 0; p < 4; p++) {
            int idx = tid + 256 * p;
            int e  = idx >> 4;
            int t8 = (idx & 15) << 3;
            int eg = eh * 64 + e;
            uint4 uv = *(const uint4*)(ubase + (size_t)eg * T_ + t8);
            const __nv_bfloat162* up = (const __nv_bfloat162*)&uv;
            const float* orow = os + e * QS2 + t8;
            float2 u0 = __bfloat1622float2(up[0]);
            float2 u1 = __bfloat1622float2(up[1]);
            float2 u2 = __bfloat1622float2(up[2]);
            float2 u3 = __bfloat1622float2(up[3]);
            uint4 wv = {
                packbf(u0.x * orow[0], u0.y * orow[1]),
                packbf(u1.x * orow[2], u1.y * orow[3]),
                packbf(u2.x * orow[4], u2.y * orow[5]),
                packbf(u3.x * orow[6], u3.y * orow[7])};
            *(uint4*)(wbase + (size_t)eg * T_ + t8) = wv;
        }
    }
}

// =============================================================================
// GEMM3: y = x + b_out + W_out @ w   M=512 K=1024 N=1024
// =============================================================================
__global__ __launch_bounds__(256) void gemm_out_bf16(
    const float* __restrict__ x, const float* __restrict__ bias)
{
    GEMM_DECL();
    const __nv_bfloat16* wb = g_w + (size_t)b * E_ * T_;
    GEMM_MAINLOOP(g_wo, E_, E_, wb);
    const float* xb = x + (size_t)b * C_ * T_;
    float* yp = g_y + (size_t)b * C_ * T_;
#pragma unroll
    for (int mi = 0; mi < 4; mi++) {
        int m = m0 + wm + mi * 16 + g;
        float bo0 = bias[m], bo1 = bias[m + 8];
#pragma unroll
        for (int ni = 0; ni < 4; ni++) {
            int n = n0 + wn + ni * 8 + 2 * th4;
            float2 x0 = *(const float2*)(xb + (size_t)m * T_ + n);
            float2 x1 = *(const float2*)(xb + (size_t)(m + 8) * T_ + n);
            float2 y0 = {acc[mi][ni][0] + bo0 + x0.x, acc[mi][ni][1] + bo0 + x0.y};
            float2 y1 = {acc[mi][ni][2] + bo1 + x1.x, acc[mi][ni][3] + bo1 + x1.y};
            *(float2*)(yp + (size_t)m * T_ + n)       = y0;
            *(float2*)(yp + (size_t)(m + 8) * T_ + n) = y1;
        }
    }
}

// =============================================================================
// RMSNorm over C
// =============================================================================
__global__ __launch_bounds__(256) void rms2_kernel(
    const float* __restrict__ gamma, float* __restrict__ out)
{
    __shared__ float red[8][32];
    __shared__ float rbuf[32];
    const int b = blockIdx.y;
    const int tseg = threadIdx.x & 31, cseg = threadIdx.x >> 5;
    const int t = blockIdx.x * 32 + tseg;
    const float* yb = g_y + (size_t)b * C_ * T_ + t;
    float ss = 0.f;
#pragma unroll 8
    for (int c = cseg * 64; c < cseg * 64 + 64; c++) {
        float v = yb[(size_t)c * T_];
        ss += v * v;
    }
    red[cseg][tseg] = ss;
    __syncthreads();
    if (cseg == 0) {
        float tot = 0.f;
#pragma unroll
        for (int i = 0; i < 8; i++) tot += red[i][tseg];
        rbuf[tseg] = rsqrtf(tot * (1.f / C_) + 1e-5f);
    }
    __syncthreads();
    float r = rbuf[tseg];
    float* op = out + (size_t)b * C_ * T_ + t;
#pragma unroll 8
    for (int c = cseg * 64; c < cseg * 64 + 64; c++) {
        op[(size_t)c * T_] = yb[(size_t)c * T_] * r * gamma[c];
    }
}

// =============================================================================
// launch
// =============================================================================
extern "C" void kernel_launch(void* const* d_in, const int* in_sizes, int n_in,
                              void* d_out, int out_size)
{
    const float* x      = (const float*)d_in[0];
    const float* W_in   = (const float*)d_in[1];
    const float* b_in   = (const float*)d_in[2];
    const float* W_attn = (const float*)d_in[3];
    const float* b_attn = (const float*)d_in[4];
    const float* w_q    = (const float*)d_in[5];
    const float* b_q    = (const float*)d_in[6];
    const float* w_k    = (const float*)d_in[7];
    const float* b_k    = (const float*)d_in[8];
    const float* W_out  = (const float*)d_in[9];
    const float* b_out  = (const float*)d_in[10];
    const float* gamma  = (const float*)d_in[11];
    float* out = (float*)d_out;

    __nv_bfloat16 *p_wi, *p_wa, *p_wo, *p_xb;
    cudaGetSymbolAddress((void**)&p_wi, g_wi);
    cudaGetSymbolAddress((void**)&p_wa, g_wa);
    cudaGetSymbolAddress((void**)&p_wo, g_wo);
    cudaGetSymbolAddress((void**)&p_xb, g_xb);

    conv_bf16<<<(2 * E_ * C_) / 2048, 256>>>(W_in, p_wi);
    conv_bf16<<<(QK_ * C_) / 2048, 256>>>(W_attn, p_wa);
    conv_bf16<<<(C_ * E_) / 2048, 256>>>(W_out, p_wo);
    conv_bf16<<<(B_ * C_ * T_) / 2048, 256>>>(x, p_xb);

    gemm_uv_bf16<<<dim3(T_ / 128, 2 * E_ / 128, B_), 256>>>(b_in);
    gemm_qk_bf16<<<dim3(T_ / 128, QK_ / 128, B_), 256>>>(b_attn, w_q, b_q, w_k, b_k);
    attn_bf16_kernel<<<dim3(T_ / 128, H_, B_), 256>>>();
    gemm_out_bf16<<<dim3(T_ / 128, C_ / 128, B_), 256>>>(x, b_out);
    rms2_kernel<<<dim3(T_ / 32, B_), 256>>>(gamma, out);
}